// round 1
// baseline (speedup 1.0000x reference)
#include <cuda_runtime.h>
#include <cuda_bf16.h>
#include <cstdint>

#define B_   8192
#define D_   512
#define PD_  128
#define NNEG 10
// 1/sqrt(T) with T = 0.5  ->  g = h / (||h|| * sqrt(T)),  g.g' = sim
#define INV_SQRT_T 1.41421356237309515f

// ---------------- scratch (device globals; no allocation) ----------------
static __device__ float          d_A1[(size_t)B_ * D_];        // relu(x@w1^T), 16 MB
static __device__ __nv_bfloat16  d_g [(size_t)B_ * PD_];       // normalized/scaled h, 2 MB
static __device__ float          d_partials[65536];            // per-block pair sums

// =========================================================================
// Kernel 1: A1 = relu(X @ W1^T)   (M=8192, N=512, K=512; both K-major)
// 128x128 block tile, 16x16 threads, 8x8 microtile, BK=16
// =========================================================================
__global__ __launch_bounds__(256, 2)
void gemm1_relu_k(const float* __restrict__ X, const float* __restrict__ W1)
{
    __shared__ float As[16][128];
    __shared__ float Bs[16][128];

    const int bm = blockIdx.y * 128;
    const int bn = blockIdx.x * 128;
    const int tid = threadIdx.x;
    const int tx = tid & 15;
    const int ty = tid >> 4;

    float acc[8][8];
#pragma unroll
    for (int i = 0; i < 8; i++)
#pragma unroll
        for (int j = 0; j < 8; j++) acc[i][j] = 0.f;

    for (int k0 = 0; k0 < D_; k0 += 16) {
        // load A tile (128 rows x 16 k) as float4, store transposed
#pragma unroll
        for (int l = 0; l < 2; l++) {
            int idx = tid + l * 256;        // 0..511 float4 slots
            int row = idx >> 2;
            int kk  = (idx & 3) * 4;
            float4 v = *(const float4*)(X + (size_t)(bm + row) * D_ + k0 + kk);
            As[kk + 0][row] = v.x; As[kk + 1][row] = v.y;
            As[kk + 2][row] = v.z; As[kk + 3][row] = v.w;
        }
#pragma unroll
        for (int l = 0; l < 2; l++) {
            int idx = tid + l * 256;
            int row = idx >> 2;
            int kk  = (idx & 3) * 4;
            float4 v = *(const float4*)(W1 + (size_t)(bn + row) * D_ + k0 + kk);
            Bs[kk + 0][row] = v.x; Bs[kk + 1][row] = v.y;
            Bs[kk + 2][row] = v.z; Bs[kk + 3][row] = v.w;
        }
        __syncthreads();

#pragma unroll
        for (int k = 0; k < 16; k++) {
            float4 a0 = *(const float4*)&As[k][ty * 8];
            float4 a1 = *(const float4*)&As[k][ty * 8 + 4];
            float4 b0 = *(const float4*)&Bs[k][tx * 8];
            float4 b1 = *(const float4*)&Bs[k][tx * 8 + 4];
            float ra[8] = {a0.x, a0.y, a0.z, a0.w, a1.x, a1.y, a1.z, a1.w};
            float rb[8] = {b0.x, b0.y, b0.z, b0.w, b1.x, b1.y, b1.z, b1.w};
#pragma unroll
            for (int i = 0; i < 8; i++)
#pragma unroll
                for (int j = 0; j < 8; j++)
                    acc[i][j] = fmaf(ra[i], rb[j], acc[i][j]);
        }
        __syncthreads();
    }

#pragma unroll
    for (int i = 0; i < 8; i++) {
        int row = bm + ty * 8 + i;
        float* op = d_A1 + (size_t)row * D_ + bn + tx * 8;
        float4 v0, v1;
        v0.x = fmaxf(acc[i][0], 0.f); v0.y = fmaxf(acc[i][1], 0.f);
        v0.z = fmaxf(acc[i][2], 0.f); v0.w = fmaxf(acc[i][3], 0.f);
        v1.x = fmaxf(acc[i][4], 0.f); v1.y = fmaxf(acc[i][5], 0.f);
        v1.z = fmaxf(acc[i][6], 0.f); v1.w = fmaxf(acc[i][7], 0.f);
        ((float4*)op)[0] = v0;
        ((float4*)op)[1] = v1;
    }
}

// =========================================================================
// Kernel 2: h = A1 @ W2^T  (M=8192, N=128, K=512), fused row-norm epilogue:
//   g = bf16( h * rsqrt(sum(h^2)) * (1/sqrt(T)) )
// 64x128 block tile (full N in one tile), 16x16 threads, 4x8 microtile
// =========================================================================
__global__ __launch_bounds__(256, 2)
void gemm2_norm_k(const float* __restrict__ W2)
{
    __shared__ float As[16][64];
    __shared__ float Bs[16][128];
    __shared__ float sq[64][17];
    __shared__ float scale_s[64];

    const int bm = blockIdx.y * 64;
    const int tid = threadIdx.x;
    const int tx = tid & 15;
    const int ty = tid >> 4;

    float acc[4][8];
#pragma unroll
    for (int i = 0; i < 4; i++)
#pragma unroll
        for (int j = 0; j < 8; j++) acc[i][j] = 0.f;

    for (int k0 = 0; k0 < D_; k0 += 16) {
        {   // A tile: 64 rows x 16 k = 256 float4, one per thread
            int row = tid >> 2;
            int kk  = (tid & 3) * 4;
            float4 v = *(const float4*)(d_A1 + (size_t)(bm + row) * D_ + k0 + kk);
            As[kk + 0][row] = v.x; As[kk + 1][row] = v.y;
            As[kk + 2][row] = v.z; As[kk + 3][row] = v.w;
        }
#pragma unroll
        for (int l = 0; l < 2; l++) {  // B tile: 128 rows x 16 k
            int idx = tid + l * 256;
            int row = idx >> 2;
            int kk  = (idx & 3) * 4;
            float4 v = *(const float4*)(W2 + (size_t)row * D_ + k0 + kk);
            Bs[kk + 0][row] = v.x; Bs[kk + 1][row] = v.y;
            Bs[kk + 2][row] = v.z; Bs[kk + 3][row] = v.w;
        }
        __syncthreads();

#pragma unroll
        for (int k = 0; k < 16; k++) {
            float4 a0 = *(const float4*)&As[k][ty * 4];
            float4 b0 = *(const float4*)&Bs[k][tx * 8];
            float4 b1 = *(const float4*)&Bs[k][tx * 8 + 4];
            float ra[4] = {a0.x, a0.y, a0.z, a0.w};
            float rb[8] = {b0.x, b0.y, b0.z, b0.w, b1.x, b1.y, b1.z, b1.w};
#pragma unroll
            for (int i = 0; i < 4; i++)
#pragma unroll
                for (int j = 0; j < 8; j++)
                    acc[i][j] = fmaf(ra[i], rb[j], acc[i][j]);
        }
        __syncthreads();
    }

    // row sum-of-squares partials
#pragma unroll
    for (int i = 0; i < 4; i++) {
        float s = 0.f;
#pragma unroll
        for (int j = 0; j < 8; j++) s = fmaf(acc[i][j], acc[i][j], s);
        sq[ty * 4 + i][tx] = s;
    }
    __syncthreads();
    if (tid < 64) {
        float ss = 0.f;
#pragma unroll
        for (int t = 0; t < 16; t++) ss += sq[tid][t];
        scale_s[tid] = rsqrtf(fmaxf(ss, 1e-24f)) * INV_SQRT_T;
    }
    __syncthreads();

#pragma unroll
    for (int i = 0; i < 4; i++) {
        int row = bm + ty * 4 + i;
        float sc = scale_s[ty * 4 + i];
        __nv_bfloat16* gp = d_g + (size_t)row * PD_ + tx * 8;
#pragma unroll
        for (int j = 0; j < 8; j++)
            gp[j] = __float2bfloat16(acc[i][j] * sc);
    }
}

// =========================================================================
// Kernel 3: pair logsumexp.  Half-warp (16 lanes) per pair:
//   anchor row (128 bf16) held in registers (8 f32/lane), 11 partner dots
//   via coalesced 256B row loads + 4-step butterfly, then segment lse.
// =========================================================================
__device__ __forceinline__ void unpack8(uint4 v, float* f)
{
    f[0] = __uint_as_float(v.x << 16); f[1] = __uint_as_float(v.x & 0xffff0000u);
    f[2] = __uint_as_float(v.y << 16); f[3] = __uint_as_float(v.y & 0xffff0000u);
    f[4] = __uint_as_float(v.z << 16); f[5] = __uint_as_float(v.z & 0xffff0000u);
    f[6] = __uint_as_float(v.w << 16); f[7] = __uint_as_float(v.w & 0xffff0000u);
}

__global__ __launch_bounds__(256)
void pair_k(const int* __restrict__ anchors,
            const int* __restrict__ positives,
            const int* __restrict__ negidx,
            int npairs)
{
    const int tid  = threadIdx.x;
    const int lane = tid & 15;
    const int p    = blockIdx.x * 16 + (tid >> 4);
    const bool valid = (p < npairs);
    const int pc = valid ? p : 0;

    const uint4* grow = (const uint4*)d_g;   // 16 uint4 per row

    const int a = anchors[pc];
    uint4 av = grow[(size_t)a * 16 + lane];
    float af[8];
    unpack8(av, af);

    float logit = 0.f;
#pragma unroll
    for (int j = 0; j < 11; j++) {
        int idx = (j == 0) ? positives[pc] : negidx[(size_t)pc * NNEG + (j - 1)];
        uint4 pv = grow[(size_t)idx * 16 + lane];
        float pf[8];
        unpack8(pv, pf);
        float s = 0.f;
#pragma unroll
        for (int e = 0; e < 8; e++) s = fmaf(af[e], pf[e], s);
        s += __shfl_xor_sync(0xffffffffu, s, 1);
        s += __shfl_xor_sync(0xffffffffu, s, 2);
        s += __shfl_xor_sync(0xffffffffu, s, 4);
        s += __shfl_xor_sync(0xffffffffu, s, 8);
        if (lane == j) logit = s;
    }

    // logsumexp over lanes 0..10 of this 16-lane segment
    float m = (lane < 11) ? logit : -1e30f;
    m = fmaxf(m, __shfl_xor_sync(0xffffffffu, m, 1));
    m = fmaxf(m, __shfl_xor_sync(0xffffffffu, m, 2));
    m = fmaxf(m, __shfl_xor_sync(0xffffffffu, m, 4));
    m = fmaxf(m, __shfl_xor_sync(0xffffffffu, m, 8));
    float e = (lane < 11) ? __expf(logit - m) : 0.f;
    e += __shfl_xor_sync(0xffffffffu, e, 1);
    e += __shfl_xor_sync(0xffffffffu, e, 2);
    e += __shfl_xor_sync(0xffffffffu, e, 4);
    e += __shfl_xor_sync(0xffffffffu, e, 8);
    float lse = m + __logf(e);
    float pos = __shfl_sync(0xffffffffu, logit, 0, 16);  // lane 0 of segment
    float contrib = valid ? (lse - pos) : 0.f;

    __shared__ float cs[16];
    if (lane == 0) cs[tid >> 4] = contrib;
    __syncthreads();
    if (tid < 16) {
        float c = cs[tid];
        c += __shfl_xor_sync(0xffffu, c, 1);
        c += __shfl_xor_sync(0xffffu, c, 2);
        c += __shfl_xor_sync(0xffffu, c, 4);
        c += __shfl_xor_sync(0xffffu, c, 8);
        if (tid == 0) d_partials[blockIdx.x] = c;
    }
}

// =========================================================================
// Kernel 4: deterministic final reduction -> mean loss
// =========================================================================
__global__ void finalize_k(int nblocks, int npairs, float* __restrict__ out)
{
    __shared__ float sm[256];
    float s = 0.f;
    for (int i = threadIdx.x; i < nblocks; i += 256) s += d_partials[i];
    sm[threadIdx.x] = s;
    __syncthreads();
    for (int w = 128; w > 0; w >>= 1) {
        if (threadIdx.x < w) sm[threadIdx.x] += sm[threadIdx.x + w];
        __syncthreads();
    }
    if (threadIdx.x == 0) out[0] = sm[0] / (float)npairs;
}

// =========================================================================
extern "C" void kernel_launch(void* const* d_in, const int* in_sizes, int n_in,
                              void* d_out, int out_size)
{
    const float* x        = (const float*)d_in[0];   // (8192, 512)
    const float* w1       = (const float*)d_in[1];   // (512, 512)
    const float* w2       = (const float*)d_in[2];   // (128, 512)
    // d_in[3] = targets (unused)
    const int*   anchors  = (const int*)d_in[4];
    const int*   positives= (const int*)d_in[5];
    const int*   negidx   = (const int*)d_in[6];
    const int npairs = in_sizes[4];

    dim3 g1(D_ / 128, B_ / 128);       // (4, 64)
    gemm1_relu_k<<<g1, 256>>>(x, w1);

    dim3 g2(1, B_ / 64);               // 128 blocks
    gemm2_norm_k<<<g2, 256>>>(w2);

    int pblocks = (npairs + 15) / 16;  // 65280 for NP=1,044,480
    pair_k<<<pblocks, 256>>>(anchors, positives, negidx, npairs);

    finalize_k<<<1, 256>>>(pblocks, npairs, (float*)d_out);
}

// round 4
// speedup vs baseline: 1.4581x; 1.4581x over previous
#include <cuda_runtime.h>
#include <cuda_bf16.h>
#include <cstdint>

#define B_   8192
#define D_   512
#define PD_  128
#define NNEG 10
#define INV_SQRT_T 1.41421356237309515f   // g = h/(||h||*sqrt(T)) so g.g' = sim

// ---------------- scratch (device globals; no allocation) ----------------
static __device__ float          d_A1[(size_t)B_ * D_];      // relu(x@w1^T), 16 MB
static __device__ __nv_bfloat16  d_g [(size_t)B_ * PD_];     // normalized h, 2 MB
static __device__ __nv_bfloat16  d_sim[(size_t)B_ * B_];     // Gram / sim, 134 MB
static __device__ float          d_partials[65536];

// =========================================================================
// Kernel 1: A1 = relu(X @ W1^T)   (M=8192, N=512, K=512)
// =========================================================================
__global__ __launch_bounds__(256, 2)
void gemm1_relu_k(const float* __restrict__ X, const float* __restrict__ W1)
{
    __shared__ float As[16][128];
    __shared__ float Bs[16][128];

    const int bm = blockIdx.y * 128;
    const int bn = blockIdx.x * 128;
    const int tid = threadIdx.x;
    const int tx = tid & 15;
    const int ty = tid >> 4;

    float acc[8][8];
#pragma unroll
    for (int i = 0; i < 8; i++)
#pragma unroll
        for (int j = 0; j < 8; j++) acc[i][j] = 0.f;

    for (int k0 = 0; k0 < D_; k0 += 16) {
#pragma unroll
        for (int l = 0; l < 2; l++) {
            int idx = tid + l * 256;
            int row = idx >> 2;
            int kk  = (idx & 3) * 4;
            float4 v = *(const float4*)(X + (size_t)(bm + row) * D_ + k0 + kk);
            As[kk + 0][row] = v.x; As[kk + 1][row] = v.y;
            As[kk + 2][row] = v.z; As[kk + 3][row] = v.w;
        }
#pragma unroll
        for (int l = 0; l < 2; l++) {
            int idx = tid + l * 256;
            int row = idx >> 2;
            int kk  = (idx & 3) * 4;
            float4 v = *(const float4*)(W1 + (size_t)(bn + row) * D_ + k0 + kk);
            Bs[kk + 0][row] = v.x; Bs[kk + 1][row] = v.y;
            Bs[kk + 2][row] = v.z; Bs[kk + 3][row] = v.w;
        }
        __syncthreads();

#pragma unroll
        for (int k = 0; k < 16; k++) {
            float4 a0 = *(const float4*)&As[k][ty * 8];
            float4 a1 = *(const float4*)&As[k][ty * 8 + 4];
            float4 b0 = *(const float4*)&Bs[k][tx * 8];
            float4 b1 = *(const float4*)&Bs[k][tx * 8 + 4];
            float ra[8] = {a0.x, a0.y, a0.z, a0.w, a1.x, a1.y, a1.z, a1.w};
            float rb[8] = {b0.x, b0.y, b0.z, b0.w, b1.x, b1.y, b1.z, b1.w};
#pragma unroll
            for (int i = 0; i < 8; i++)
#pragma unroll
                for (int j = 0; j < 8; j++)
                    acc[i][j] = fmaf(ra[i], rb[j], acc[i][j]);
        }
        __syncthreads();
    }

#pragma unroll
    for (int i = 0; i < 8; i++) {
        int row = bm + ty * 8 + i;
        float* op = d_A1 + (size_t)row * D_ + bn + tx * 8;
        float4 v0, v1;
        v0.x = fmaxf(acc[i][0], 0.f); v0.y = fmaxf(acc[i][1], 0.f);
        v0.z = fmaxf(acc[i][2], 0.f); v0.w = fmaxf(acc[i][3], 0.f);
        v1.x = fmaxf(acc[i][4], 0.f); v1.y = fmaxf(acc[i][5], 0.f);
        v1.z = fmaxf(acc[i][6], 0.f); v1.w = fmaxf(acc[i][7], 0.f);
        ((float4*)op)[0] = v0;
        ((float4*)op)[1] = v1;
    }
}

// =========================================================================
// Kernel 2: h = A1 @ W2^T, fused row-norm -> g (bf16)
// =========================================================================
__global__ __launch_bounds__(256, 2)
void gemm2_norm_k(const float* __restrict__ W2)
{
    __shared__ float As[16][64];
    __shared__ float Bs[16][128];
    __shared__ float sq[64][17];
    __shared__ float scale_s[64];

    const int bm = blockIdx.y * 64;
    const int tid = threadIdx.x;
    const int tx = tid & 15;
    const int ty = tid >> 4;

    float acc[4][8];
#pragma unroll
    for (int i = 0; i < 4; i++)
#pragma unroll
        for (int j = 0; j < 8; j++) acc[i][j] = 0.f;

    for (int k0 = 0; k0 < D_; k0 += 16) {
        {
            int row = tid >> 2;
            int kk  = (tid & 3) * 4;
            float4 v = *(const float4*)(d_A1 + (size_t)(bm + row) * D_ + k0 + kk);
            As[kk + 0][row] = v.x; As[kk + 1][row] = v.y;
            As[kk + 2][row] = v.z; As[kk + 3][row] = v.w;
        }
#pragma unroll
        for (int l = 0; l < 2; l++) {
            int idx = tid + l * 256;
            int row = idx >> 2;
            int kk  = (idx & 3) * 4;
            float4 v = *(const float4*)(W2 + (size_t)row * D_ + k0 + kk);
            Bs[kk + 0][row] = v.x; Bs[kk + 1][row] = v.y;
            Bs[kk + 2][row] = v.z; Bs[kk + 3][row] = v.w;
        }
        __syncthreads();

#pragma unroll
        for (int k = 0; k < 16; k++) {
            float4 a0 = *(const float4*)&As[k][ty * 4];
            float4 b0 = *(const float4*)&Bs[k][tx * 8];
            float4 b1 = *(const float4*)&Bs[k][tx * 8 + 4];
            float ra[4] = {a0.x, a0.y, a0.z, a0.w};
            float rb[8] = {b0.x, b0.y, b0.z, b0.w, b1.x, b1.y, b1.z, b1.w};
#pragma unroll
            for (int i = 0; i < 4; i++)
#pragma unroll
                for (int j = 0; j < 8; j++)
                    acc[i][j] = fmaf(ra[i], rb[j], acc[i][j]);
        }
        __syncthreads();
    }

#pragma unroll
    for (int i = 0; i < 4; i++) {
        float s = 0.f;
#pragma unroll
        for (int j = 0; j < 8; j++) s = fmaf(acc[i][j], acc[i][j], s);
        sq[ty * 4 + i][tx] = s;
    }
    __syncthreads();
    if (tid < 64) {
        float ss = 0.f;
#pragma unroll
        for (int t = 0; t < 16; t++) ss += sq[tid][t];
        scale_s[tid] = rsqrtf(fmaxf(ss, 1e-24f)) * INV_SQRT_T;
    }
    __syncthreads();

#pragma unroll
    for (int i = 0; i < 4; i++) {
        int row = bm + ty * 4 + i;
        float sc = scale_s[ty * 4 + i];
        __nv_bfloat16* gp = d_g + (size_t)row * PD_ + tx * 8;
#pragma unroll
        for (int j = 0; j < 8; j++)
            gp[j] = __float2bfloat16(acc[i][j] * sc);
    }
}

// =========================================================================
// Kernel 3: Gram matrix  sim = g @ g^T  via mma.sync m16n8k16 bf16 (HMMA)
// 128x128 CTA tile, K=128 single shot. 8 warps (2x4), each 64x32 out.
// SMEM tiles row-major [128][136] bf16 (pad 8 -> +4 banks per row).
// Epilogue staged through SMEM for coalesced 16B/lane stores.
// =========================================================================
#define TSTRIDE 136
#define GRAM_SMEM_BYTES (2 * 128 * TSTRIDE * 2)   // 69632

__global__ __launch_bounds__(256, 2)
void gram_k()
{
    extern __shared__ __nv_bfloat16 smg[];
    __nv_bfloat16* As = smg;                    // [128][136]
    __nv_bfloat16* Bs = smg + 128 * TSTRIDE;    // [128][136]

    const int tid  = threadIdx.x;
    const int wid  = tid >> 5;
    const int lane = tid & 31;
    const int m0 = blockIdx.y * 128;
    const int n0 = blockIdx.x * 128;

    // ---- load A (rows m0..+127) and B (rows n0..+127) tiles of g ----
    const uint4* grow = (const uint4*)d_g;      // 16 uint4 per 128-elem row
#pragma unroll
    for (int i = 0; i < 8; i++) {
        int id = tid + i * 256;                 // 0..2047
        int r  = id >> 4;
        int ch = id & 15;
        uint4 va = grow[(size_t)(m0 + r) * 16 + ch];
        uint4 vb = grow[(size_t)(n0 + r) * 16 + ch];
        *(uint4*)(As + r * TSTRIDE + ch * 8) = va;
        *(uint4*)(Bs + r * TSTRIDE + ch * 8) = vb;
    }
    __syncthreads();

    // ---- warp tiling ----
    const int wm = (wid >> 2) * 64;             // 0 or 64
    const int wn = (wid & 3) * 32;              // 0,32,64,96
    const int qr = lane >> 2;                   // 0..7
    const int qc = (lane & 3) * 2;              // 0,2,4,6

    float acc[4][4][4];
#pragma unroll
    for (int mi = 0; mi < 4; mi++)
#pragma unroll
        for (int nj = 0; nj < 4; nj++)
#pragma unroll
            for (int q = 0; q < 4; q++) acc[mi][nj][q] = 0.f;

#pragma unroll
    for (int ks = 0; ks < 8; ks++) {
        uint32_t a[4][4], b[4][2];
#pragma unroll
        for (int mi = 0; mi < 4; mi++) {
            const __nv_bfloat16* ap = As + (wm + 16 * mi + qr) * TSTRIDE + ks * 16 + qc;
            a[mi][0] = *(const uint32_t*)(ap);
            a[mi][1] = *(const uint32_t*)(ap + 8 * TSTRIDE);
            a[mi][2] = *(const uint32_t*)(ap + 8);
            a[mi][3] = *(const uint32_t*)(ap + 8 * TSTRIDE + 8);
        }
#pragma unroll
        for (int nj = 0; nj < 4; nj++) {
            const __nv_bfloat16* bp = Bs + (wn + 8 * nj + qr) * TSTRIDE + ks * 16 + qc;
            b[nj][0] = *(const uint32_t*)(bp);
            b[nj][1] = *(const uint32_t*)(bp + 8);
        }
#pragma unroll
        for (int mi = 0; mi < 4; mi++)
#pragma unroll
            for (int nj = 0; nj < 4; nj++)
                asm volatile(
                    "mma.sync.aligned.m16n8k16.row.col.f32.bf16.bf16.f32 "
                    "{%0,%1,%2,%3}, {%4,%5,%6,%7}, {%8,%9}, {%0,%1,%2,%3};"
                    : "+f"(acc[mi][nj][0]), "+f"(acc[mi][nj][1]),
                      "+f"(acc[mi][nj][2]), "+f"(acc[mi][nj][3])
                    : "r"(a[mi][0]), "r"(a[mi][1]), "r"(a[mi][2]), "r"(a[mi][3]),
                      "r"(b[nj][0]), "r"(b[nj][1]));
    }

    // ---- epilogue: stage bf16 tile in SMEM, then coalesced copy-out ----
    __syncthreads();                             // SMEM reuse (As region)
    __nv_bfloat16* Es = As;                      // [128][136]
#pragma unroll
    for (int mi = 0; mi < 4; mi++)
#pragma unroll
        for (int nj = 0; nj < 4; nj++) {
            int r0 = wm + 16 * mi + qr;
            int c0 = wn + 8 * nj + qc;
            __nv_bfloat162 lo = __floats2bfloat162_rn(acc[mi][nj][0], acc[mi][nj][1]);
            __nv_bfloat162 hi = __floats2bfloat162_rn(acc[mi][nj][2], acc[mi][nj][3]);
            *(__nv_bfloat162*)(Es + r0 * TSTRIDE + c0) = lo;
            *(__nv_bfloat162*)(Es + (r0 + 8) * TSTRIDE + c0) = hi;
        }
    __syncthreads();

#pragma unroll
    for (int i = 0; i < 8; i++) {
        int id = tid + i * 256;
        int r  = id >> 4;
        int ch = id & 15;
        uint4 v = *(const uint4*)(Es + r * TSTRIDE + ch * 8);
        *(uint4*)(d_sim + (size_t)(m0 + r) * B_ + n0 + ch * 8) = v;
    }
}

// =========================================================================
// Kernel 4: gather 11 sims per pair + logsumexp, block-sum partials
// =========================================================================
__global__ __launch_bounds__(256)
void gather_lse_k(const int* __restrict__ anchors,
                  const int* __restrict__ positives,
                  const int* __restrict__ negidx,
                  int npairs)
{
    const int tid = threadIdx.x;
    const int p = blockIdx.x * 256 + tid;
    const bool valid = (p < npairs);
    const int pc = valid ? p : 0;

    const int a = anchors[pc];
    const __nv_bfloat16* __restrict__ row = d_sim + (size_t)a * B_;

    int pidx = positives[pc];
    int nid[NNEG];
#pragma unroll
    for (int j = 0; j < NNEG; j++) nid[j] = negidx[(size_t)pc * NNEG + j];

    float pos = __bfloat162float(row[pidx]);
    float ln[NNEG];
#pragma unroll
    for (int j = 0; j < NNEG; j++) ln[j] = __bfloat162float(row[nid[j]]);

    float m = pos;
#pragma unroll
    for (int j = 0; j < NNEG; j++) m = fmaxf(m, ln[j]);
    float se = __expf(pos - m);
#pragma unroll
    for (int j = 0; j < NNEG; j++) se += __expf(ln[j] - m);
    float contrib = valid ? (m + __logf(se) - pos) : 0.f;

    contrib += __shfl_xor_sync(0xffffffffu, contrib, 1);
    contrib += __shfl_xor_sync(0xffffffffu, contrib, 2);
    contrib += __shfl_xor_sync(0xffffffffu, contrib, 4);
    contrib += __shfl_xor_sync(0xffffffffu, contrib, 8);
    contrib += __shfl_xor_sync(0xffffffffu, contrib, 16);
    __shared__ float ws[8];
    if ((tid & 31) == 0) ws[tid >> 5] = contrib;
    __syncthreads();
    if (tid < 8) {
        float c = ws[tid];
        c += __shfl_xor_sync(0xffu, c, 1);
        c += __shfl_xor_sync(0xffu, c, 2);
        c += __shfl_xor_sync(0xffu, c, 4);
        if (tid == 0) d_partials[blockIdx.x] = c;
    }
}

// =========================================================================
// Kernel 5: deterministic final reduction -> mean loss
// =========================================================================
__global__ void finalize_k(int nblocks, int npairs, float* __restrict__ out)
{
    __shared__ float sm[256];
    float s = 0.f;
    for (int i = threadIdx.x; i < nblocks; i += 256) s += d_partials[i];
    sm[threadIdx.x] = s;
    __syncthreads();
    for (int w = 128; w > 0; w >>= 1) {
        if (threadIdx.x < w) sm[threadIdx.x] += sm[threadIdx.x + w];
        __syncthreads();
    }
    if (threadIdx.x == 0) out[0] = sm[0] / (float)npairs;
}

// =========================================================================
extern "C" void kernel_launch(void* const* d_in, const int* in_sizes, int n_in,
                              void* d_out, int out_size)
{
    const float* x        = (const float*)d_in[0];
    const float* w1       = (const float*)d_in[1];
    const float* w2       = (const float*)d_in[2];
    const int*   anchors  = (const int*)d_in[4];
    const int*   positives= (const int*)d_in[5];
    const int*   negidx   = (const int*)d_in[6];
    const int npairs = in_sizes[4];

    dim3 g1(D_ / 128, B_ / 128);
    gemm1_relu_k<<<g1, 256>>>(x, w1);

    dim3 g2(1, B_ / 64);
    gemm2_norm_k<<<g2, 256>>>(w2);

    static int smem_set = 0;
    if (!smem_set) {
        cudaFuncSetAttribute(gram_k, cudaFuncAttributeMaxDynamicSharedMemorySize,
                             GRAM_SMEM_BYTES);
        smem_set = 1;
    }
    dim3 gg(B_ / 128, B_ / 128);      // 64 x 64 tiles
    gram_k<<<gg, 256, GRAM_SMEM_BYTES>>>();

    int pblocks = (npairs + 255) / 256;
    gather_lse_k<<<pblocks, 256>>>(anchors, positives, negidx, npairs);

    finalize_k<<<1, 256>>>(pblocks, npairs, (float*)d_out);
}

// round 5
// speedup vs baseline: 2.2244x; 1.5255x over previous
#include <cuda_runtime.h>
#include <cuda_bf16.h>
#include <cstdint>

#define B_   8192
#define D_   512
#define PD_  128
#define NNEG 10
#define INV_SQRT_T 1.41421356237309515f   // g = h/(||h||*sqrt(T)) so g.g' = sim

// ---------------- scratch (device globals; no allocation) ----------------
static __device__ float          d_A1[(size_t)B_ * D_];      // relu(x@w1^T), 16 MB
static __device__ __nv_bfloat16  d_g [(size_t)B_ * PD_];     // normalized h, 2 MB
static __device__ __nv_bfloat16  d_sim[(size_t)B_ * B_];     // Gram (upper), 134 MB
static __device__ float          d_partials[65536];

__device__ __forceinline__ uint32_t f2tf32(float f) {
    uint32_t r;
    asm("cvt.rna.tf32.f32 %0, %1;" : "=r"(r) : "f"(f));
    return r;
}

// =========================================================================
// Kernel 1: A1 = relu(X @ W1^T) via tf32 mma.sync (M=8192, N=512, K=512)
// 128x128 CTA tile, BK=32. 8 warps (2x4), warp tile 64x32.
// SMEM [row][k] stride 36 -> fragment LDS bank = (4r+qc)%32, conflict-free.
// =========================================================================
#define TFS 36
__global__ __launch_bounds__(256, 2)
void gemm1_tf32_k(const float* __restrict__ X, const float* __restrict__ W1)
{
    __shared__ uint32_t As[128 * TFS];
    __shared__ uint32_t Bs[128 * TFS];

    const int tid  = threadIdx.x;
    const int wid  = tid >> 5;
    const int lane = tid & 31;
    const int bm = blockIdx.y * 128;
    const int bn = blockIdx.x * 128;

    const int wm = (wid >> 2) * 64;
    const int wn = (wid & 3) * 32;
    const int qr = lane >> 2;        // 0..7
    const int qc = lane & 3;         // 0..3

    float acc[4][4][4];
#pragma unroll
    for (int mi = 0; mi < 4; mi++)
#pragma unroll
        for (int nj = 0; nj < 4; nj++)
#pragma unroll
            for (int q = 0; q < 4; q++) acc[mi][nj][q] = 0.f;

    for (int k0 = 0; k0 < D_; k0 += 32) {
        // stage tiles (128 rows x 32 k), converting fp32 -> tf32
#pragma unroll
        for (int l = 0; l < 4; l++) {
            int id = tid + l * 256;              // 0..1023
            int r  = id >> 3;
            int c4 = (id & 7) * 4;
            float4 v = *(const float4*)(X + (size_t)(bm + r) * D_ + k0 + c4);
            uint32_t* ap = As + r * TFS + c4;
            ap[0] = f2tf32(v.x); ap[1] = f2tf32(v.y);
            ap[2] = f2tf32(v.z); ap[3] = f2tf32(v.w);
            float4 w = *(const float4*)(W1 + (size_t)(bn + r) * D_ + k0 + c4);
            uint32_t* bp = Bs + r * TFS + c4;
            bp[0] = f2tf32(w.x); bp[1] = f2tf32(w.y);
            bp[2] = f2tf32(w.z); bp[3] = f2tf32(w.w);
        }
        __syncthreads();

#pragma unroll
        for (int ks = 0; ks < 4; ks++) {
            uint32_t a[4][4], b[4][2];
#pragma unroll
            for (int mi = 0; mi < 4; mi++) {
                const uint32_t* ap = As + (wm + 16 * mi + qr) * TFS + ks * 8 + qc;
                a[mi][0] = ap[0];
                a[mi][1] = ap[8 * TFS];
                a[mi][2] = ap[4];
                a[mi][3] = ap[8 * TFS + 4];
            }
#pragma unroll
            for (int nj = 0; nj < 4; nj++) {
                const uint32_t* bp = Bs + (wn + 8 * nj + qr) * TFS + ks * 8 + qc;
                b[nj][0] = bp[0];
                b[nj][1] = bp[4];
            }
#pragma unroll
            for (int mi = 0; mi < 4; mi++)
#pragma unroll
                for (int nj = 0; nj < 4; nj++)
                    asm volatile(
                        "mma.sync.aligned.m16n8k8.row.col.f32.tf32.tf32.f32 "
                        "{%0,%1,%2,%3}, {%4,%5,%6,%7}, {%8,%9}, {%0,%1,%2,%3};"
                        : "+f"(acc[mi][nj][0]), "+f"(acc[mi][nj][1]),
                          "+f"(acc[mi][nj][2]), "+f"(acc[mi][nj][3])
                        : "r"(a[mi][0]), "r"(a[mi][1]), "r"(a[mi][2]), "r"(a[mi][3]),
                          "r"(b[nj][0]), "r"(b[nj][1]));
        }
        __syncthreads();
    }

    // epilogue: relu + direct float2 stores
#pragma unroll
    for (int mi = 0; mi < 4; mi++)
#pragma unroll
        for (int nj = 0; nj < 4; nj++) {
            int row = bm + wm + 16 * mi + qr;
            int col = bn + wn + 8 * nj + qc * 2;
            float2 v0, v1;
            v0.x = fmaxf(acc[mi][nj][0], 0.f);
            v0.y = fmaxf(acc[mi][nj][1], 0.f);
            v1.x = fmaxf(acc[mi][nj][2], 0.f);
            v1.y = fmaxf(acc[mi][nj][3], 0.f);
            *(float2*)(d_A1 + (size_t)row * D_ + col) = v0;
            *(float2*)(d_A1 + (size_t)(row + 8) * D_ + col) = v1;
        }
}

// =========================================================================
// Kernel 2: h = A1 @ W2^T, fused row-norm -> g (bf16)
// =========================================================================
__global__ __launch_bounds__(256, 2)
void gemm2_norm_k(const float* __restrict__ W2)
{
    __shared__ float As[16][64];
    __shared__ float Bs[16][128];
    __shared__ float sq[64][17];
    __shared__ float scale_s[64];

    const int bm = blockIdx.y * 64;
    const int tid = threadIdx.x;
    const int tx = tid & 15;
    const int ty = tid >> 4;

    float acc[4][8];
#pragma unroll
    for (int i = 0; i < 4; i++)
#pragma unroll
        for (int j = 0; j < 8; j++) acc[i][j] = 0.f;

    for (int k0 = 0; k0 < D_; k0 += 16) {
        {
            int row = tid >> 2;
            int kk  = (tid & 3) * 4;
            float4 v = *(const float4*)(d_A1 + (size_t)(bm + row) * D_ + k0 + kk);
            As[kk + 0][row] = v.x; As[kk + 1][row] = v.y;
            As[kk + 2][row] = v.z; As[kk + 3][row] = v.w;
        }
#pragma unroll
        for (int l = 0; l < 2; l++) {
            int idx = tid + l * 256;
            int row = idx >> 2;
            int kk  = (idx & 3) * 4;
            float4 v = *(const float4*)(W2 + (size_t)row * D_ + k0 + kk);
            Bs[kk + 0][row] = v.x; Bs[kk + 1][row] = v.y;
            Bs[kk + 2][row] = v.z; Bs[kk + 3][row] = v.w;
        }
        __syncthreads();

#pragma unroll
        for (int k = 0; k < 16; k++) {
            float4 a0 = *(const float4*)&As[k][ty * 4];
            float4 b0 = *(const float4*)&Bs[k][tx * 8];
            float4 b1 = *(const float4*)&Bs[k][tx * 8 + 4];
            float ra[4] = {a0.x, a0.y, a0.z, a0.w};
            float rb[8] = {b0.x, b0.y, b0.z, b0.w, b1.x, b1.y, b1.z, b1.w};
#pragma unroll
            for (int i = 0; i < 4; i++)
#pragma unroll
                for (int j = 0; j < 8; j++)
                    acc[i][j] = fmaf(ra[i], rb[j], acc[i][j]);
        }
        __syncthreads();
    }

#pragma unroll
    for (int i = 0; i < 4; i++) {
        float s = 0.f;
#pragma unroll
        for (int j = 0; j < 8; j++) s = fmaf(acc[i][j], acc[i][j], s);
        sq[ty * 4 + i][tx] = s;
    }
    __syncthreads();
    if (tid < 64) {
        float ss = 0.f;
#pragma unroll
        for (int t = 0; t < 16; t++) ss += sq[tid][t];
        scale_s[tid] = rsqrtf(fmaxf(ss, 1e-24f)) * INV_SQRT_T;
    }
    __syncthreads();

#pragma unroll
    for (int i = 0; i < 4; i++) {
        int row = bm + ty * 4 + i;
        float sc = scale_s[ty * 4 + i];
        __nv_bfloat16* gp = d_g + (size_t)row * PD_ + tx * 8;
#pragma unroll
        for (int j = 0; j < 8; j++)
            gp[j] = __float2bfloat16(acc[i][j] * sc);
    }
}

// =========================================================================
// Kernel 3: Gram (UPPER TRIANGLE ONLY): sim = g @ g^T via bf16 HMMA
// Tiles with blockIdx.x >= blockIdx.y only; gather reads [min][max].
// =========================================================================
#define TSTRIDE 136
#define GRAM_SMEM_BYTES (2 * 128 * TSTRIDE * 2)   // 69632

__global__ __launch_bounds__(256, 2)
void gram_k()
{
    if (blockIdx.x < blockIdx.y) return;          // lower-triangle tile: skip

    extern __shared__ __nv_bfloat16 smg[];
    __nv_bfloat16* As = smg;                      // [128][136]
    __nv_bfloat16* Bs = smg + 128 * TSTRIDE;      // [128][136]

    const int tid  = threadIdx.x;
    const int wid  = tid >> 5;
    const int lane = tid & 31;
    const int m0 = blockIdx.y * 128;
    const int n0 = blockIdx.x * 128;

    const uint4* grow = (const uint4*)d_g;
#pragma unroll
    for (int i = 0; i < 8; i++) {
        int id = tid + i * 256;
        int r  = id >> 4;
        int ch = id & 15;
        uint4 va = grow[(size_t)(m0 + r) * 16 + ch];
        uint4 vb = grow[(size_t)(n0 + r) * 16 + ch];
        *(uint4*)(As + r * TSTRIDE + ch * 8) = va;
        *(uint4*)(Bs + r * TSTRIDE + ch * 8) = vb;
    }
    __syncthreads();

    const int wm = (wid >> 2) * 64;
    const int wn = (wid & 3) * 32;
    const int qr = lane >> 2;
    const int qc = (lane & 3) * 2;

    float acc[4][4][4];
#pragma unroll
    for (int mi = 0; mi < 4; mi++)
#pragma unroll
        for (int nj = 0; nj < 4; nj++)
#pragma unroll
            for (int q = 0; q < 4; q++) acc[mi][nj][q] = 0.f;

#pragma unroll
    for (int ks = 0; ks < 8; ks++) {
        uint32_t a[4][4], b[4][2];
#pragma unroll
        for (int mi = 0; mi < 4; mi++) {
            const __nv_bfloat16* ap = As + (wm + 16 * mi + qr) * TSTRIDE + ks * 16 + qc;
            a[mi][0] = *(const uint32_t*)(ap);
            a[mi][1] = *(const uint32_t*)(ap + 8 * TSTRIDE);
            a[mi][2] = *(const uint32_t*)(ap + 8);
            a[mi][3] = *(const uint32_t*)(ap + 8 * TSTRIDE + 8);
        }
#pragma unroll
        for (int nj = 0; nj < 4; nj++) {
            const __nv_bfloat16* bp = Bs + (wn + 8 * nj + qr) * TSTRIDE + ks * 16 + qc;
            b[nj][0] = *(const uint32_t*)(bp);
            b[nj][1] = *(const uint32_t*)(bp + 8);
        }
#pragma unroll
        for (int mi = 0; mi < 4; mi++)
#pragma unroll
            for (int nj = 0; nj < 4; nj++)
                asm volatile(
                    "mma.sync.aligned.m16n8k16.row.col.f32.bf16.bf16.f32 "
                    "{%0,%1,%2,%3}, {%4,%5,%6,%7}, {%8,%9}, {%0,%1,%2,%3};"
                    : "+f"(acc[mi][nj][0]), "+f"(acc[mi][nj][1]),
                      "+f"(acc[mi][nj][2]), "+f"(acc[mi][nj][3])
                    : "r"(a[mi][0]), "r"(a[mi][1]), "r"(a[mi][2]), "r"(a[mi][3]),
                      "r"(b[nj][0]), "r"(b[nj][1]));
    }

    // stage bf16 tile in SMEM, then coalesced copy-out
    __syncthreads();
    __nv_bfloat16* Es = As;
#pragma unroll
    for (int mi = 0; mi < 4; mi++)
#pragma unroll
        for (int nj = 0; nj < 4; nj++) {
            int r0 = wm + 16 * mi + qr;
            int c0 = wn + 8 * nj + qc;
            __nv_bfloat162 lo = __floats2bfloat162_rn(acc[mi][nj][0], acc[mi][nj][1]);
            __nv_bfloat162 hi = __floats2bfloat162_rn(acc[mi][nj][2], acc[mi][nj][3]);
            *(__nv_bfloat162*)(Es + r0 * TSTRIDE + c0) = lo;
            *(__nv_bfloat162*)(Es + (r0 + 8) * TSTRIDE + c0) = hi;
        }
    __syncthreads();

#pragma unroll
    for (int i = 0; i < 8; i++) {
        int id = tid + i * 256;
        int r  = id >> 4;
        int ch = id & 15;
        uint4 v = *(const uint4*)(Es + r * TSTRIDE + ch * 8);
        *(uint4*)(d_sim + (size_t)(m0 + r) * B_ + n0 + ch * 8) = v;
    }
}

// =========================================================================
// Kernel 4: gather 11 sims per pair (upper-triangle indexed) + logsumexp
// =========================================================================
__global__ __launch_bounds__(256)
void gather_lse_k(const int* __restrict__ anchors,
                  const int* __restrict__ positives,
                  const int* __restrict__ negidx,
                  int npairs)
{
    const int tid = threadIdx.x;
    const int p = blockIdx.x * 256 + tid;
    const bool valid = (p < npairs);
    const int pc = valid ? p : 0;

    const int a = anchors[pc];

    int pidx = positives[pc];
    int nid[NNEG];
#pragma unroll
    for (int j = 0; j < NNEG; j++) nid[j] = negidx[(size_t)pc * NNEG + j];

    {   // positive
        int r = min(a, pidx), c = max(a, pidx);
        pidx = 0;  // reuse var below via pos
        float posv = __bfloat162float(d_sim[(size_t)r * B_ + c]);
        float ln[NNEG];
#pragma unroll
        for (int j = 0; j < NNEG; j++) {
            int rr = min(a, nid[j]), cc = max(a, nid[j]);
            ln[j] = __bfloat162float(d_sim[(size_t)rr * B_ + cc]);
        }

        float m = posv;
#pragma unroll
        for (int j = 0; j < NNEG; j++) m = fmaxf(m, ln[j]);
        float se = __expf(posv - m);
#pragma unroll
        for (int j = 0; j < NNEG; j++) se += __expf(ln[j] - m);
        float contrib = valid ? (m + __logf(se) - posv) : 0.f;

        contrib += __shfl_xor_sync(0xffffffffu, contrib, 1);
        contrib += __shfl_xor_sync(0xffffffffu, contrib, 2);
        contrib += __shfl_xor_sync(0xffffffffu, contrib, 4);
        contrib += __shfl_xor_sync(0xffffffffu, contrib, 8);
        contrib += __shfl_xor_sync(0xffffffffu, contrib, 16);
        __shared__ float ws[8];
        if ((tid & 31) == 0) ws[tid >> 5] = contrib;
        __syncthreads();
        if (tid < 8) {
            float cv = ws[tid];
            cv += __shfl_xor_sync(0xffu, cv, 1);
            cv += __shfl_xor_sync(0xffu, cv, 2);
            cv += __shfl_xor_sync(0xffu, cv, 4);
            if (tid == 0) d_partials[blockIdx.x] = cv;
        }
    }
}

// =========================================================================
// Kernel 5: deterministic final reduction -> mean loss
// =========================================================================
__global__ void finalize_k(int nblocks, int npairs, float* __restrict__ out)
{
    __shared__ float sm[256];
    float s = 0.f;
    for (int i = threadIdx.x; i < nblocks; i += 256) s += d_partials[i];
    sm[threadIdx.x] = s;
    __syncthreads();
    for (int w = 128; w > 0; w >>= 1) {
        if (threadIdx.x < w) sm[threadIdx.x] += sm[threadIdx.x + w];
        __syncthreads();
    }
    if (threadIdx.x == 0) out[0] = sm[0] / (float)npairs;
}

// =========================================================================
extern "C" void kernel_launch(void* const* d_in, const int* in_sizes, int n_in,
                              void* d_out, int out_size)
{
    const float* x        = (const float*)d_in[0];
    const float* w1       = (const float*)d_in[1];
    const float* w2       = (const float*)d_in[2];
    const int*   anchors  = (const int*)d_in[4];
    const int*   positives= (const int*)d_in[5];
    const int*   negidx   = (const int*)d_in[6];
    const int npairs = in_sizes[4];

    dim3 g1(D_ / 128, B_ / 128);     // (4, 64)
    gemm1_tf32_k<<<g1, 256>>>(x, w1);

    dim3 g2(1, B_ / 64);
    gemm2_norm_k<<<g2, 256>>>(w2);

    static int smem_set = 0;
    if (!smem_set) {
        cudaFuncSetAttribute(gram_k, cudaFuncAttributeMaxDynamicSharedMemorySize,
                             GRAM_SMEM_BYTES);
        smem_set = 1;
    }
    dim3 gg(B_ / 128, B_ / 128);     // 64 x 64, lower tiles early-exit
    gram_k<<<gg, 256, GRAM_SMEM_BYTES>>>();

    int pblocks = (npairs + 255) / 256;
    gather_lse_k<<<pblocks, 256>>>(anchors, positives, negidx, npairs);

    finalize_k<<<1, 256>>>(pblocks, npairs, (float*)d_out);
}

// round 6
// speedup vs baseline: 2.9910x; 1.3446x over previous
#include <cuda_runtime.h>
#include <cuda_bf16.h>
#include <cstdint>

#define B_   8192
#define D_   512
#define PD_  128
#define NNEG 10
#define INV_SQRT_T 1.41421356237309515f   // g = h/(||h||*sqrt(T)) so g.g' = sim

// ---------------- scratch (device globals; no allocation) ----------------
static __device__ float          d_A1[(size_t)B_ * D_];      // relu(x@w1^T), 16 MB
static __device__ __nv_bfloat16  d_g [(size_t)B_ * PD_];     // normalized h, 2 MB
static __device__ __nv_bfloat16  d_sim[(size_t)B_ * B_];     // Gram (upper), 134 MB
static __device__ float          d_partials[65536];

__device__ __forceinline__ uint32_t f2tf32(float f) {
    uint32_t r;
    asm("cvt.rna.tf32.f32 %0, %1;" : "=r"(r) : "f"(f));
    return r;
}
__device__ __forceinline__ uint32_t smem_addr(const void* p) {
    return (uint32_t)__cvta_generic_to_shared(p);
}

// =========================================================================
// Kernel 1: A1 = relu(X @ W1^T) via tf32 mma.sync (M=8192, N=512, K=512)
// 128x128 CTA tile, BK=32. 8 warps (2x4), warp tile 64x32.
// =========================================================================
#define TFS 36
__global__ __launch_bounds__(256, 2)
void gemm1_tf32_k(const float* __restrict__ X, const float* __restrict__ W1)
{
    __shared__ uint32_t As[128 * TFS];
    __shared__ uint32_t Bs[128 * TFS];

    const int tid  = threadIdx.x;
    const int wid  = tid >> 5;
    const int lane = tid & 31;
    const int bm = blockIdx.y * 128;
    const int bn = blockIdx.x * 128;

    const int wm = (wid >> 2) * 64;
    const int wn = (wid & 3) * 32;
    const int qr = lane >> 2;
    const int qc = lane & 3;

    float acc[4][4][4];
#pragma unroll
    for (int mi = 0; mi < 4; mi++)
#pragma unroll
        for (int nj = 0; nj < 4; nj++)
#pragma unroll
            for (int q = 0; q < 4; q++) acc[mi][nj][q] = 0.f;

    for (int k0 = 0; k0 < D_; k0 += 32) {
#pragma unroll
        for (int l = 0; l < 4; l++) {
            int id = tid + l * 256;
            int r  = id >> 3;
            int c4 = (id & 7) * 4;
            float4 v = *(const float4*)(X + (size_t)(bm + r) * D_ + k0 + c4);
            uint32_t* ap = As + r * TFS + c4;
            ap[0] = f2tf32(v.x); ap[1] = f2tf32(v.y);
            ap[2] = f2tf32(v.z); ap[3] = f2tf32(v.w);
            float4 w = *(const float4*)(W1 + (size_t)(bn + r) * D_ + k0 + c4);
            uint32_t* bp = Bs + r * TFS + c4;
            bp[0] = f2tf32(w.x); bp[1] = f2tf32(w.y);
            bp[2] = f2tf32(w.z); bp[3] = f2tf32(w.w);
        }
        __syncthreads();

#pragma unroll
        for (int ks = 0; ks < 4; ks++) {
            uint32_t a[4][4], b[4][2];
#pragma unroll
            for (int mi = 0; mi < 4; mi++) {
                const uint32_t* ap = As + (wm + 16 * mi + qr) * TFS + ks * 8 + qc;
                a[mi][0] = ap[0];
                a[mi][1] = ap[8 * TFS];
                a[mi][2] = ap[4];
                a[mi][3] = ap[8 * TFS + 4];
            }
#pragma unroll
            for (int nj = 0; nj < 4; nj++) {
                const uint32_t* bp = Bs + (wn + 8 * nj + qr) * TFS + ks * 8 + qc;
                b[nj][0] = bp[0];
                b[nj][1] = bp[4];
            }
#pragma unroll
            for (int mi = 0; mi < 4; mi++)
#pragma unroll
                for (int nj = 0; nj < 4; nj++)
                    asm volatile(
                        "mma.sync.aligned.m16n8k8.row.col.f32.tf32.tf32.f32 "
                        "{%0,%1,%2,%3}, {%4,%5,%6,%7}, {%8,%9}, {%0,%1,%2,%3};"
                        : "+f"(acc[mi][nj][0]), "+f"(acc[mi][nj][1]),
                          "+f"(acc[mi][nj][2]), "+f"(acc[mi][nj][3])
                        : "r"(a[mi][0]), "r"(a[mi][1]), "r"(a[mi][2]), "r"(a[mi][3]),
                          "r"(b[nj][0]), "r"(b[nj][1]));
        }
        __syncthreads();
    }

#pragma unroll
    for (int mi = 0; mi < 4; mi++)
#pragma unroll
        for (int nj = 0; nj < 4; nj++) {
            int row = bm + wm + 16 * mi + qr;
            int col = bn + wn + 8 * nj + qc * 2;
            float2 v0, v1;
            v0.x = fmaxf(acc[mi][nj][0], 0.f);
            v0.y = fmaxf(acc[mi][nj][1], 0.f);
            v1.x = fmaxf(acc[mi][nj][2], 0.f);
            v1.y = fmaxf(acc[mi][nj][3], 0.f);
            *(float2*)(d_A1 + (size_t)row * D_ + col) = v0;
            *(float2*)(d_A1 + (size_t)(row + 8) * D_ + col) = v1;
        }
}

// =========================================================================
// Kernel 2: h = A1 @ W2^T via tf32 mma.sync, fused row-norm -> g (bf16)
// 64x128 CTA tile (full N in-CTA), BK=32, 8 warps (2x4), warp tile 32x32.
// =========================================================================
__global__ __launch_bounds__(256, 2)
void gemm2_tf32_k(const float* __restrict__ W2)
{
    __shared__ uint32_t As[64 * TFS];     // 9216 words
    __shared__ uint32_t Bs[128 * TFS];    // 18432 words
    __shared__ float sqp[64][4];
    __shared__ float scale_s[64];

    const int tid  = threadIdx.x;
    const int wid  = tid >> 5;
    const int lane = tid & 31;
    const int bm = blockIdx.x * 64;

    const int wm = (wid >> 2) * 32;       // 0 or 32
    const int wn = (wid & 3) * 32;        // 0..96
    const int qr = lane >> 2;
    const int qc = lane & 3;

    float acc[2][4][4];
#pragma unroll
    for (int mi = 0; mi < 2; mi++)
#pragma unroll
        for (int nj = 0; nj < 4; nj++)
#pragma unroll
            for (int q = 0; q < 4; q++) acc[mi][nj][q] = 0.f;

    for (int k0 = 0; k0 < D_; k0 += 32) {
#pragma unroll
        for (int l = 0; l < 2; l++) {     // A: 64x32 = 512 float4
            int id = tid + l * 256;
            int r  = id >> 3;
            int c4 = (id & 7) * 4;
            float4 v = *(const float4*)(d_A1 + (size_t)(bm + r) * D_ + k0 + c4);
            uint32_t* ap = As + r * TFS + c4;
            ap[0] = f2tf32(v.x); ap[1] = f2tf32(v.y);
            ap[2] = f2tf32(v.z); ap[3] = f2tf32(v.w);
        }
#pragma unroll
        for (int l = 0; l < 4; l++) {     // B: 128x32 = 1024 float4
            int id = tid + l * 256;
            int r  = id >> 3;
            int c4 = (id & 7) * 4;
            float4 w = *(const float4*)(W2 + (size_t)r * D_ + k0 + c4);
            uint32_t* bp = Bs + r * TFS + c4;
            bp[0] = f2tf32(w.x); bp[1] = f2tf32(w.y);
            bp[2] = f2tf32(w.z); bp[3] = f2tf32(w.w);
        }
        __syncthreads();

#pragma unroll
        for (int ks = 0; ks < 4; ks++) {
            uint32_t a[2][4], b[4][2];
#pragma unroll
            for (int mi = 0; mi < 2; mi++) {
                const uint32_t* ap = As + (wm + 16 * mi + qr) * TFS + ks * 8 + qc;
                a[mi][0] = ap[0];
                a[mi][1] = ap[8 * TFS];
                a[mi][2] = ap[4];
                a[mi][3] = ap[8 * TFS + 4];
            }
#pragma unroll
            for (int nj = 0; nj < 4; nj++) {
                const uint32_t* bp = Bs + (wn + 8 * nj + qr) * TFS + ks * 8 + qc;
                b[nj][0] = bp[0];
                b[nj][1] = bp[4];
            }
#pragma unroll
            for (int mi = 0; mi < 2; mi++)
#pragma unroll
                for (int nj = 0; nj < 4; nj++)
                    asm volatile(
                        "mma.sync.aligned.m16n8k8.row.col.f32.tf32.tf32.f32 "
                        "{%0,%1,%2,%3}, {%4,%5,%6,%7}, {%8,%9}, {%0,%1,%2,%3};"
                        : "+f"(acc[mi][nj][0]), "+f"(acc[mi][nj][1]),
                          "+f"(acc[mi][nj][2]), "+f"(acc[mi][nj][3])
                        : "r"(a[mi][0]), "r"(a[mi][1]), "r"(a[mi][2]), "r"(a[mi][3]),
                          "r"(b[nj][0]), "r"(b[nj][1]));
        }
        __syncthreads();
    }

    // ---- fused row-norm: sum h^2 over the 128 columns of each row ----
#pragma unroll
    for (int mi = 0; mi < 2; mi++) {
        float s0 = 0.f, s1 = 0.f;
#pragma unroll
        for (int nj = 0; nj < 4; nj++) {
            s0 = fmaf(acc[mi][nj][0], acc[mi][nj][0], s0);
            s0 = fmaf(acc[mi][nj][1], acc[mi][nj][1], s0);
            s1 = fmaf(acc[mi][nj][2], acc[mi][nj][2], s1);
            s1 = fmaf(acc[mi][nj][3], acc[mi][nj][3], s1);
        }
        // reduce across the 4 lanes sharing qr (qc = 0..3)
        s0 += __shfl_xor_sync(0xffffffffu, s0, 1);
        s0 += __shfl_xor_sync(0xffffffffu, s0, 2);
        s1 += __shfl_xor_sync(0xffffffffu, s1, 1);
        s1 += __shfl_xor_sync(0xffffffffu, s1, 2);
        if (qc == 0) {
            sqp[wm + 16 * mi + qr][wid & 3]     = s0;
            sqp[wm + 16 * mi + qr + 8][wid & 3] = s1;
        }
    }
    __syncthreads();
    if (tid < 64) {
        float ss = sqp[tid][0] + sqp[tid][1] + sqp[tid][2] + sqp[tid][3];
        scale_s[tid] = rsqrtf(fmaxf(ss, 1e-24f)) * INV_SQRT_T;
    }
    __syncthreads();

#pragma unroll
    for (int mi = 0; mi < 2; mi++)
#pragma unroll
        for (int nj = 0; nj < 4; nj++) {
            int r0 = wm + 16 * mi + qr;
            int col = wn + 8 * nj + qc * 2;
            float sc0 = scale_s[r0];
            float sc1 = scale_s[r0 + 8];
            __nv_bfloat162 lo = __floats2bfloat162_rn(acc[mi][nj][0] * sc0,
                                                      acc[mi][nj][1] * sc0);
            __nv_bfloat162 hi = __floats2bfloat162_rn(acc[mi][nj][2] * sc1,
                                                      acc[mi][nj][3] * sc1);
            *(__nv_bfloat162*)(d_g + (size_t)(bm + r0) * PD_ + col) = lo;
            *(__nv_bfloat162*)(d_g + (size_t)(bm + r0 + 8) * PD_ + col) = hi;
        }
}

// =========================================================================
// Kernel 3: Gram (UPPER TRIANGLE): sim = g @ g^T via bf16 HMMA + ldmatrix
// =========================================================================
#define TSTRIDE 136
#define GRAM_SMEM_BYTES (2 * 128 * TSTRIDE * 2)   // 69632

__global__ __launch_bounds__(256, 2)
void gram_k()
{
    if (blockIdx.x < blockIdx.y) return;

    extern __shared__ __nv_bfloat16 smg[];
    __nv_bfloat16* As = smg;
    __nv_bfloat16* Bs = smg + 128 * TSTRIDE;

    const int tid  = threadIdx.x;
    const int wid  = tid >> 5;
    const int lane = tid & 31;
    const int m0 = blockIdx.y * 128;
    const int n0 = blockIdx.x * 128;

    const uint4* grow = (const uint4*)d_g;
#pragma unroll
    for (int i = 0; i < 8; i++) {
        int id = tid + i * 256;
        int r  = id >> 4;
        int ch = id & 15;
        uint4 va = grow[(size_t)(m0 + r) * 16 + ch];
        uint4 vb = grow[(size_t)(n0 + r) * 16 + ch];
        *(uint4*)(As + r * TSTRIDE + ch * 8) = va;
        *(uint4*)(Bs + r * TSTRIDE + ch * 8) = vb;
    }
    __syncthreads();

    const int wm = (wid >> 2) * 64;
    const int wn = (wid & 3) * 32;
    const int qr = lane >> 2;
    const int qc = (lane & 3) * 2;

    // ldmatrix lane addressing
    const int a_row = lane & 15;            // + 16*mi + wm
    const int a_kof = (lane >> 4) * 8;      // k half
    const int g3    = lane >> 3;            // 0..3
    const int b_row = 8 * (g3 >> 1) + (lane & 7);  // + 16*nj2 + wn
    const int b_kof = 8 * (g3 & 1);

    float acc[4][4][4];
#pragma unroll
    for (int mi = 0; mi < 4; mi++)
#pragma unroll
        for (int nj = 0; nj < 4; nj++)
#pragma unroll
            for (int q = 0; q < 4; q++) acc[mi][nj][q] = 0.f;

#pragma unroll
    for (int ks = 0; ks < 8; ks++) {
        uint32_t a[4][4], b[4][2];
#pragma unroll
        for (int mi = 0; mi < 4; mi++) {
            uint32_t ad = smem_addr(As + (wm + 16 * mi + a_row) * TSTRIDE
                                       + ks * 16 + a_kof);
            asm volatile("ldmatrix.sync.aligned.m8n8.x4.shared.b16 "
                         "{%0,%1,%2,%3}, [%4];"
                         : "=r"(a[mi][0]), "=r"(a[mi][1]),
                           "=r"(a[mi][2]), "=r"(a[mi][3]) : "r"(ad));
        }
#pragma unroll
        for (int nj2 = 0; nj2 < 2; nj2++) {
            uint32_t bd = smem_addr(Bs + (wn + 16 * nj2 + b_row) * TSTRIDE
                                       + ks * 16 + b_kof);
            asm volatile("ldmatrix.sync.aligned.m8n8.x4.shared.b16 "
                         "{%0,%1,%2,%3}, [%4];"
                         : "=r"(b[2 * nj2][0]), "=r"(b[2 * nj2][1]),
                           "=r"(b[2 * nj2 + 1][0]), "=r"(b[2 * nj2 + 1][1])
                         : "r"(bd));
        }
#pragma unroll
        for (int mi = 0; mi < 4; mi++)
#pragma unroll
            for (int nj = 0; nj < 4; nj++)
                asm volatile(
                    "mma.sync.aligned.m16n8k16.row.col.f32.bf16.bf16.f32 "
                    "{%0,%1,%2,%3}, {%4,%5,%6,%7}, {%8,%9}, {%0,%1,%2,%3};"
                    : "+f"(acc[mi][nj][0]), "+f"(acc[mi][nj][1]),
                      "+f"(acc[mi][nj][2]), "+f"(acc[mi][nj][3])
                    : "r"(a[mi][0]), "r"(a[mi][1]), "r"(a[mi][2]), "r"(a[mi][3]),
                      "r"(b[nj][0]), "r"(b[nj][1]));
    }

    __syncthreads();
    __nv_bfloat16* Es = As;
#pragma unroll
    for (int mi = 0; mi < 4; mi++)
#pragma unroll
        for (int nj = 0; nj < 4; nj++) {
            int r0 = wm + 16 * mi + qr;
            int c0 = wn + 8 * nj + qc;
            __nv_bfloat162 lo = __floats2bfloat162_rn(acc[mi][nj][0], acc[mi][nj][1]);
            __nv_bfloat162 hi = __floats2bfloat162_rn(acc[mi][nj][2], acc[mi][nj][3]);
            *(__nv_bfloat162*)(Es + r0 * TSTRIDE + c0) = lo;
            *(__nv_bfloat162*)(Es + (r0 + 8) * TSTRIDE + c0) = hi;
        }
    __syncthreads();

#pragma unroll
    for (int i = 0; i < 8; i++) {
        int id = tid + i * 256;
        int r  = id >> 4;
        int ch = id & 15;
        uint4 v = *(const uint4*)(Es + r * TSTRIDE + ch * 8);
        *(uint4*)(d_sim + (size_t)(m0 + r) * B_ + n0 + ch * 8) = v;
    }
}

// =========================================================================
// Kernel 4: gather 11 sims per pair (upper-triangle indexed) + logsumexp
// =========================================================================
__global__ __launch_bounds__(256)
void gather_lse_k(const int* __restrict__ anchors,
                  const int* __restrict__ positives,
                  const int* __restrict__ negidx,
                  int npairs)
{
    const int tid = threadIdx.x;
    const int p = blockIdx.x * 256 + tid;
    const bool valid = (p < npairs);
    const int pc = valid ? p : 0;

    const int a = anchors[pc];
    int pidx = positives[pc];
    int nid[NNEG];
#pragma unroll
    for (int j = 0; j < NNEG; j++) nid[j] = negidx[(size_t)pc * NNEG + j];

    int r = min(a, pidx), c = max(a, pidx);
    float posv = __bfloat162float(d_sim[(size_t)r * B_ + c]);
    float ln[NNEG];
#pragma unroll
    for (int j = 0; j < NNEG; j++) {
        int rr = min(a, nid[j]), cc = max(a, nid[j]);
        ln[j] = __bfloat162float(d_sim[(size_t)rr * B_ + cc]);
    }

    float m = posv;
#pragma unroll
    for (int j = 0; j < NNEG; j++) m = fmaxf(m, ln[j]);
    float se = __expf(posv - m);
#pragma unroll
    for (int j = 0; j < NNEG; j++) se += __expf(ln[j] - m);
    float contrib = valid ? (m + __logf(se) - posv) : 0.f;

    contrib += __shfl_xor_sync(0xffffffffu, contrib, 1);
    contrib += __shfl_xor_sync(0xffffffffu, contrib, 2);
    contrib += __shfl_xor_sync(0xffffffffu, contrib, 4);
    contrib += __shfl_xor_sync(0xffffffffu, contrib, 8);
    contrib += __shfl_xor_sync(0xffffffffu, contrib, 16);
    __shared__ float ws[8];
    if ((tid & 31) == 0) ws[tid >> 5] = contrib;
    __syncthreads();
    if (tid < 8) {
        float cv = ws[tid];
        cv += __shfl_xor_sync(0xffu, cv, 1);
        cv += __shfl_xor_sync(0xffu, cv, 2);
        cv += __shfl_xor_sync(0xffu, cv, 4);
        if (tid == 0) d_partials[blockIdx.x] = cv;
    }
}

// =========================================================================
// Kernel 5: deterministic final reduction -> mean loss
// =========================================================================
__global__ void finalize_k(int nblocks, int npairs, float* __restrict__ out)
{
    __shared__ float sm[256];
    float s = 0.f;
    for (int i = threadIdx.x; i < nblocks; i += 256) s += d_partials[i];
    sm[threadIdx.x] = s;
    __syncthreads();
    for (int w = 128; w > 0; w >>= 1) {
        if (threadIdx.x < w) sm[threadIdx.x] += sm[threadIdx.x + w];
        __syncthreads();
    }
    if (threadIdx.x == 0) out[0] = sm[0] / (float)npairs;
}

// =========================================================================
extern "C" void kernel_launch(void* const* d_in, const int* in_sizes, int n_in,
                              void* d_out, int out_size)
{
    const float* x        = (const float*)d_in[0];
    const float* w1       = (const float*)d_in[1];
    const float* w2       = (const float*)d_in[2];
    const int*   anchors  = (const int*)d_in[4];
    const int*   positives= (const int*)d_in[5];
    const int*   negidx   = (const int*)d_in[6];
    const int npairs = in_sizes[4];

    dim3 g1(D_ / 128, B_ / 128);     // (4, 64)
    gemm1_tf32_k<<<g1, 256>>>(x, w1);

    gemm2_tf32_k<<<B_ / 64, 256>>>(w2);   // 128 CTAs

    static int smem_set = 0;
    if (!smem_set) {
        cudaFuncSetAttribute(gram_k, cudaFuncAttributeMaxDynamicSharedMemorySize,
                             GRAM_SMEM_BYTES);
        smem_set = 1;
    }
    dim3 gg(B_ / 128, B_ / 128);
    gram_k<<<gg, 256, GRAM_SMEM_BYTES>>>();

    int pblocks = (npairs + 255) / 256;
    gather_lse_k<<<pblocks, 256>>>(anchors, positives, negidx, npairs);

    finalize_k<<<1, 256>>>(pblocks, npairs, (float*)d_out);
}

// round 7
// speedup vs baseline: 3.3569x; 1.1223x over previous
#include <cuda_runtime.h>
#include <cuda_bf16.h>
#include <cstdint>

#define B_   8192
#define D_   512
#define PD_  128
#define NNEG 10
#define INV_SQRT_T 1.41421356237309515f   // g = h/(||h||*sqrt(T)) so g.g' = sim

// ---------------- scratch (device globals; no allocation) ----------------
static __device__ float          d_A1[(size_t)B_ * D_];      // relu(x@w1^T), 16 MB
static __device__ __nv_bfloat16  d_g [(size_t)B_ * PD_];     // normalized h, 2 MB
static __device__ __nv_bfloat16  d_sim[(size_t)B_ * B_];     // Gram (upper), 134 MB
static __device__ float          d_partials[65536];

__device__ __forceinline__ uint32_t smem_addr(const void* p) {
    return (uint32_t)__cvta_generic_to_shared(p);
}
#define CP_ASYNC16(dst, src) \
    asm volatile("cp.async.cg.shared.global [%0], [%1], 16;" :: "r"(dst), "l"(src))
#define CP_COMMIT() asm volatile("cp.async.commit_group;" ::: "memory")
#define CP_WAIT1()  asm volatile("cp.async.wait_group 1;" ::: "memory")

// =========================================================================
// Kernel 1: A1 = relu(X @ W1^T) via tf32 mma.sync, cp.async double-buffered
// 128x128 CTA tile, BK=32. 8 warps (2x4), warp tile 64x32.
// Raw fp32 bits fed as tf32 (HW truncates mantissa; uniform shrink cancels
// under the downstream row normalization).
// =========================================================================
#define TFS 36
#define G1_TILE (128 * TFS)                       // words per tile
#define G1_SMEM_BYTES (4 * G1_TILE * 4)           // 2 bufs x (A+B) = 73728 B

__global__ __launch_bounds__(256, 2)
void gemm1_tf32_k(const float* __restrict__ X, const float* __restrict__ W1)
{
    extern __shared__ uint32_t dynsm[];
    uint32_t* Asb = dynsm;                        // [2][128*TFS]
    uint32_t* Bsb = dynsm + 2 * G1_TILE;          // [2][128*TFS]

    const int tid  = threadIdx.x;
    const int wid  = tid >> 5;
    const int lane = tid & 31;
    const int bm = blockIdx.y * 128;
    const int bn = blockIdx.x * 128;

    const int wm = (wid >> 2) * 64;
    const int wn = (wid & 3) * 32;
    const int qr = lane >> 2;
    const int qc = lane & 3;

    // per-thread staging coords (4 chunks of 16B for A, 4 for B)
    int srow[4], scol[4];
#pragma unroll
    for (int l = 0; l < 4; l++) {
        int id = tid + l * 256;
        srow[l] = id >> 3;
        scol[l] = (id & 7) * 4;
    }

    float acc[4][4][4];
#pragma unroll
    for (int mi = 0; mi < 4; mi++)
#pragma unroll
        for (int nj = 0; nj < 4; nj++)
#pragma unroll
            for (int q = 0; q < 4; q++) acc[mi][nj][q] = 0.f;

    // prologue: stage k0=0 into buffer 0
#pragma unroll
    for (int l = 0; l < 4; l++) {
        CP_ASYNC16(smem_addr(Asb + srow[l] * TFS + scol[l]),
                   X + (size_t)(bm + srow[l]) * D_ + scol[l]);
        CP_ASYNC16(smem_addr(Bsb + srow[l] * TFS + scol[l]),
                   W1 + (size_t)(bn + srow[l]) * D_ + scol[l]);
    }
    CP_COMMIT();

    const int NIT = D_ / 32;                      // 16
    for (int it = 0; it < NIT; it++) {
        if (it + 1 < NIT) {
            int kn = (it + 1) * 32;
            uint32_t boff = ((it + 1) & 1) * G1_TILE;
#pragma unroll
            for (int l = 0; l < 4; l++) {
                CP_ASYNC16(smem_addr(Asb + boff + srow[l] * TFS + scol[l]),
                           X + (size_t)(bm + srow[l]) * D_ + kn + scol[l]);
                CP_ASYNC16(smem_addr(Bsb + boff + srow[l] * TFS + scol[l]),
                           W1 + (size_t)(bn + srow[l]) * D_ + kn + scol[l]);
            }
        }
        CP_COMMIT();
        CP_WAIT1();
        __syncthreads();

        const uint32_t* As = Asb + (it & 1) * G1_TILE;
        const uint32_t* Bs = Bsb + (it & 1) * G1_TILE;
#pragma unroll
        for (int ks = 0; ks < 4; ks++) {
            uint32_t a[4][4], b[4][2];
#pragma unroll
            for (int mi = 0; mi < 4; mi++) {
                const uint32_t* ap = As + (wm + 16 * mi + qr) * TFS + ks * 8 + qc;
                a[mi][0] = ap[0];
                a[mi][1] = ap[8 * TFS];
                a[mi][2] = ap[4];
                a[mi][3] = ap[8 * TFS + 4];
            }
#pragma unroll
            for (int nj = 0; nj < 4; nj++) {
                const uint32_t* bp = Bs + (wn + 8 * nj + qr) * TFS + ks * 8 + qc;
                b[nj][0] = bp[0];
                b[nj][1] = bp[4];
            }
#pragma unroll
            for (int mi = 0; mi < 4; mi++)
#pragma unroll
                for (int nj = 0; nj < 4; nj++)
                    asm volatile(
                        "mma.sync.aligned.m16n8k8.row.col.f32.tf32.tf32.f32 "
                        "{%0,%1,%2,%3}, {%4,%5,%6,%7}, {%8,%9}, {%0,%1,%2,%3};"
                        : "+f"(acc[mi][nj][0]), "+f"(acc[mi][nj][1]),
                          "+f"(acc[mi][nj][2]), "+f"(acc[mi][nj][3])
                        : "r"(a[mi][0]), "r"(a[mi][1]), "r"(a[mi][2]), "r"(a[mi][3]),
                          "r"(b[nj][0]), "r"(b[nj][1]));
        }
        __syncthreads();
    }

#pragma unroll
    for (int mi = 0; mi < 4; mi++)
#pragma unroll
        for (int nj = 0; nj < 4; nj++) {
            int row = bm + wm + 16 * mi + qr;
            int col = bn + wn + 8 * nj + qc * 2;
            float2 v0, v1;
            v0.x = fmaxf(acc[mi][nj][0], 0.f);
            v0.y = fmaxf(acc[mi][nj][1], 0.f);
            v1.x = fmaxf(acc[mi][nj][2], 0.f);
            v1.y = fmaxf(acc[mi][nj][3], 0.f);
            *(float2*)(d_A1 + (size_t)row * D_ + col) = v0;
            *(float2*)(d_A1 + (size_t)(row + 8) * D_ + col) = v1;
        }
}

// =========================================================================
// Kernel 2: h = A1 @ W2^T via tf32 mma.sync (cp.async double-buffered),
// fused row-norm -> g (bf16). 64x128 CTA tile, 8 warps (2x4), 32x32/warp.
// =========================================================================
#define G2_ATILE (64 * TFS)
#define G2_BTILE (128 * TFS)
#define G2_SMEM_BYTES (2 * (G2_ATILE + G2_BTILE) * 4)   // 55296 B

__global__ __launch_bounds__(256, 2)
void gemm2_tf32_k(const float* __restrict__ W2)
{
    extern __shared__ uint32_t dynsm[];
    uint32_t* Asb = dynsm;                        // [2][64*TFS]
    uint32_t* Bsb = dynsm + 2 * G2_ATILE;         // [2][128*TFS]
    __shared__ float sqp[64][4];
    __shared__ float scale_s[64];

    const int tid  = threadIdx.x;
    const int wid  = tid >> 5;
    const int lane = tid & 31;
    const int bm = blockIdx.x * 64;

    const int wm = (wid >> 2) * 32;
    const int wn = (wid & 3) * 32;
    const int qr = lane >> 2;
    const int qc = lane & 3;

    int srow[4], scol[4];
#pragma unroll
    for (int l = 0; l < 4; l++) {
        int id = tid + l * 256;
        srow[l] = id >> 3;
        scol[l] = (id & 7) * 4;
    }

    float acc[2][4][4];
#pragma unroll
    for (int mi = 0; mi < 2; mi++)
#pragma unroll
        for (int nj = 0; nj < 4; nj++)
#pragma unroll
            for (int q = 0; q < 4; q++) acc[mi][nj][q] = 0.f;

    // prologue
#pragma unroll
    for (int l = 0; l < 2; l++)
        CP_ASYNC16(smem_addr(Asb + srow[l] * TFS + scol[l]),
                   d_A1 + (size_t)(bm + srow[l]) * D_ + scol[l]);
#pragma unroll
    for (int l = 0; l < 4; l++)
        CP_ASYNC16(smem_addr(Bsb + srow[l] * TFS + scol[l]),
                   W2 + (size_t)srow[l] * D_ + scol[l]);
    CP_COMMIT();

    const int NIT = D_ / 32;
    for (int it = 0; it < NIT; it++) {
        if (it + 1 < NIT) {
            int kn = (it + 1) * 32;
            uint32_t ab = ((it + 1) & 1) * G2_ATILE;
            uint32_t bb = ((it + 1) & 1) * G2_BTILE;
#pragma unroll
            for (int l = 0; l < 2; l++)
                CP_ASYNC16(smem_addr(Asb + ab + srow[l] * TFS + scol[l]),
                           d_A1 + (size_t)(bm + srow[l]) * D_ + kn + scol[l]);
#pragma unroll
            for (int l = 0; l < 4; l++)
                CP_ASYNC16(smem_addr(Bsb + bb + srow[l] * TFS + scol[l]),
                           W2 + (size_t)srow[l] * D_ + kn + scol[l]);
        }
        CP_COMMIT();
        CP_WAIT1();
        __syncthreads();

        const uint32_t* As = Asb + (it & 1) * G2_ATILE;
        const uint32_t* Bs = Bsb + (it & 1) * G2_BTILE;
#pragma unroll
        for (int ks = 0; ks < 4; ks++) {
            uint32_t a[2][4], b[4][2];
#pragma unroll
            for (int mi = 0; mi < 2; mi++) {
                const uint32_t* ap = As + (wm + 16 * mi + qr) * TFS + ks * 8 + qc;
                a[mi][0] = ap[0];
                a[mi][1] = ap[8 * TFS];
                a[mi][2] = ap[4];
                a[mi][3] = ap[8 * TFS + 4];
            }
#pragma unroll
            for (int nj = 0; nj < 4; nj++) {
                const uint32_t* bp = Bs + (wn + 8 * nj + qr) * TFS + ks * 8 + qc;
                b[nj][0] = bp[0];
                b[nj][1] = bp[4];
            }
#pragma unroll
            for (int mi = 0; mi < 2; mi++)
#pragma unroll
                for (int nj = 0; nj < 4; nj++)
                    asm volatile(
                        "mma.sync.aligned.m16n8k8.row.col.f32.tf32.tf32.f32 "
                        "{%0,%1,%2,%3}, {%4,%5,%6,%7}, {%8,%9}, {%0,%1,%2,%3};"
                        : "+f"(acc[mi][nj][0]), "+f"(acc[mi][nj][1]),
                          "+f"(acc[mi][nj][2]), "+f"(acc[mi][nj][3])
                        : "r"(a[mi][0]), "r"(a[mi][1]), "r"(a[mi][2]), "r"(a[mi][3]),
                          "r"(b[nj][0]), "r"(b[nj][1]));
        }
        __syncthreads();
    }

    // ---- fused row-norm ----
#pragma unroll
    for (int mi = 0; mi < 2; mi++) {
        float s0 = 0.f, s1 = 0.f;
#pragma unroll
        for (int nj = 0; nj < 4; nj++) {
            s0 = fmaf(acc[mi][nj][0], acc[mi][nj][0], s0);
            s0 = fmaf(acc[mi][nj][1], acc[mi][nj][1], s0);
            s1 = fmaf(acc[mi][nj][2], acc[mi][nj][2], s1);
            s1 = fmaf(acc[mi][nj][3], acc[mi][nj][3], s1);
        }
        s0 += __shfl_xor_sync(0xffffffffu, s0, 1);
        s0 += __shfl_xor_sync(0xffffffffu, s0, 2);
        s1 += __shfl_xor_sync(0xffffffffu, s1, 1);
        s1 += __shfl_xor_sync(0xffffffffu, s1, 2);
        if (qc == 0) {
            sqp[wm + 16 * mi + qr][wid & 3]     = s0;
            sqp[wm + 16 * mi + qr + 8][wid & 3] = s1;
        }
    }
    __syncthreads();
    if (tid < 64) {
        float ss = sqp[tid][0] + sqp[tid][1] + sqp[tid][2] + sqp[tid][3];
        scale_s[tid] = rsqrtf(fmaxf(ss, 1e-24f)) * INV_SQRT_T;
    }
    __syncthreads();

#pragma unroll
    for (int mi = 0; mi < 2; mi++)
#pragma unroll
        for (int nj = 0; nj < 4; nj++) {
            int r0 = wm + 16 * mi + qr;
            int col = wn + 8 * nj + qc * 2;
            float sc0 = scale_s[r0];
            float sc1 = scale_s[r0 + 8];
            __nv_bfloat162 lo = __floats2bfloat162_rn(acc[mi][nj][0] * sc0,
                                                      acc[mi][nj][1] * sc0);
            __nv_bfloat162 hi = __floats2bfloat162_rn(acc[mi][nj][2] * sc1,
                                                      acc[mi][nj][3] * sc1);
            *(__nv_bfloat162*)(d_g + (size_t)(bm + r0) * PD_ + col) = lo;
            *(__nv_bfloat162*)(d_g + (size_t)(bm + r0 + 8) * PD_ + col) = hi;
        }
}

// =========================================================================
// Kernel 3: Gram (UPPER TRIANGLE): sim = g @ g^T via bf16 HMMA + ldmatrix
// =========================================================================
#define TSTRIDE 136
#define GRAM_SMEM_BYTES (2 * 128 * TSTRIDE * 2)   // 69632

__global__ __launch_bounds__(256, 2)
void gram_k()
{
    if (blockIdx.x < blockIdx.y) return;

    extern __shared__ __nv_bfloat16 smg[];
    __nv_bfloat16* As = smg;
    __nv_bfloat16* Bs = smg + 128 * TSTRIDE;

    const int tid  = threadIdx.x;
    const int wid  = tid >> 5;
    const int lane = tid & 31;
    const int m0 = blockIdx.y * 128;
    const int n0 = blockIdx.x * 128;

    const uint4* grow = (const uint4*)d_g;
#pragma unroll
    for (int i = 0; i < 8; i++) {
        int id = tid + i * 256;
        int r  = id >> 4;
        int ch = id & 15;
        uint4 va = grow[(size_t)(m0 + r) * 16 + ch];
        uint4 vb = grow[(size_t)(n0 + r) * 16 + ch];
        *(uint4*)(As + r * TSTRIDE + ch * 8) = va;
        *(uint4*)(Bs + r * TSTRIDE + ch * 8) = vb;
    }
    __syncthreads();

    const int wm = (wid >> 2) * 64;
    const int wn = (wid & 3) * 32;
    const int qr = lane >> 2;
    const int qc = (lane & 3) * 2;

    const int a_row = lane & 15;
    const int a_kof = (lane >> 4) * 8;
    const int g3    = lane >> 3;
    const int b_row = 8 * (g3 >> 1) + (lane & 7);
    const int b_kof = 8 * (g3 & 1);

    float acc[4][4][4];
#pragma unroll
    for (int mi = 0; mi < 4; mi++)
#pragma unroll
        for (int nj = 0; nj < 4; nj++)
#pragma unroll
            for (int q = 0; q < 4; q++) acc[mi][nj][q] = 0.f;

#pragma unroll
    for (int ks = 0; ks < 8; ks++) {
        uint32_t a[4][4], b[4][2];
#pragma unroll
        for (int mi = 0; mi < 4; mi++) {
            uint32_t ad = smem_addr(As + (wm + 16 * mi + a_row) * TSTRIDE
                                       + ks * 16 + a_kof);
            asm volatile("ldmatrix.sync.aligned.m8n8.x4.shared.b16 "
                         "{%0,%1,%2,%3}, [%4];"
                         : "=r"(a[mi][0]), "=r"(a[mi][1]),
                           "=r"(a[mi][2]), "=r"(a[mi][3]) : "r"(ad));
        }
#pragma unroll
        for (int nj2 = 0; nj2 < 2; nj2++) {
            uint32_t bd = smem_addr(Bs + (wn + 16 * nj2 + b_row) * TSTRIDE
                                       + ks * 16 + b_kof);
            asm volatile("ldmatrix.sync.aligned.m8n8.x4.shared.b16 "
                         "{%0,%1,%2,%3}, [%4];"
                         : "=r"(b[2 * nj2][0]), "=r"(b[2 * nj2][1]),
                           "=r"(b[2 * nj2 + 1][0]), "=r"(b[2 * nj2 + 1][1])
                         : "r"(bd));
        }
#pragma unroll
        for (int mi = 0; mi < 4; mi++)
#pragma unroll
            for (int nj = 0; nj < 4; nj++)
                asm volatile(
                    "mma.sync.aligned.m16n8k16.row.col.f32.bf16.bf16.f32 "
                    "{%0,%1,%2,%3}, {%4,%5,%6,%7}, {%8,%9}, {%0,%1,%2,%3};"
                    : "+f"(acc[mi][nj][0]), "+f"(acc[mi][nj][1]),
                      "+f"(acc[mi][nj][2]), "+f"(acc[mi][nj][3])
                    : "r"(a[mi][0]), "r"(a[mi][1]), "r"(a[mi][2]), "r"(a[mi][3]),
                      "r"(b[nj][0]), "r"(b[nj][1]));
    }

    __syncthreads();
    __nv_bfloat16* Es = As;
#pragma unroll
    for (int mi = 0; mi < 4; mi++)
#pragma unroll
        for (int nj = 0; nj < 4; nj++) {
            int r0 = wm + 16 * mi + qr;
            int c0 = wn + 8 * nj + qc;
            __nv_bfloat162 lo = __floats2bfloat162_rn(acc[mi][nj][0], acc[mi][nj][1]);
            __nv_bfloat162 hi = __floats2bfloat162_rn(acc[mi][nj][2], acc[mi][nj][3]);
            *(__nv_bfloat162*)(Es + r0 * TSTRIDE + c0) = lo;
            *(__nv_bfloat162*)(Es + (r0 + 8) * TSTRIDE + c0) = hi;
        }
    __syncthreads();

#pragma unroll
    for (int i = 0; i < 8; i++) {
        int id = tid + i * 256;
        int r  = id >> 4;
        int ch = id & 15;
        uint4 v = *(const uint4*)(Es + r * TSTRIDE + ch * 8);
        *(uint4*)(d_sim + (size_t)(m0 + r) * B_ + n0 + ch * 8) = v;
    }
}

// =========================================================================
// Kernel 4: gather 11 sims per pair (upper-triangle indexed) + logsumexp
// =========================================================================
__global__ __launch_bounds__(256)
void gather_lse_k(const int* __restrict__ anchors,
                  const int* __restrict__ positives,
                  const int* __restrict__ negidx,
                  int npairs)
{
    const int tid = threadIdx.x;
    const int p = blockIdx.x * 256 + tid;
    const bool valid = (p < npairs);
    const int pc = valid ? p : 0;

    const int a = anchors[pc];
    int pidx = positives[pc];
    int nid[NNEG];
#pragma unroll
    for (int j = 0; j < NNEG; j++) nid[j] = negidx[(size_t)pc * NNEG + j];

    int r = min(a, pidx), c = max(a, pidx);
    float posv = __bfloat162float(d_sim[(size_t)r * B_ + c]);
    float ln[NNEG];
#pragma unroll
    for (int j = 0; j < NNEG; j++) {
        int rr = min(a, nid[j]), cc = max(a, nid[j]);
        ln[j] = __bfloat162float(d_sim[(size_t)rr * B_ + cc]);
    }

    float m = posv;
#pragma unroll
    for (int j = 0; j < NNEG; j++) m = fmaxf(m, ln[j]);
    float se = __expf(posv - m);
#pragma unroll
    for (int j = 0; j < NNEG; j++) se += __expf(ln[j] - m);
    float contrib = valid ? (m + __logf(se) - posv) : 0.f;

    contrib += __shfl_xor_sync(0xffffffffu, contrib, 1);
    contrib += __shfl_xor_sync(0xffffffffu, contrib, 2);
    contrib += __shfl_xor_sync(0xffffffffu, contrib, 4);
    contrib += __shfl_xor_sync(0xffffffffu, contrib, 8);
    contrib += __shfl_xor_sync(0xffffffffu, contrib, 16);
    __shared__ float ws[8];
    if ((tid & 31) == 0) ws[tid >> 5] = contrib;
    __syncthreads();
    if (tid < 8) {
        float cv = ws[tid];
        cv += __shfl_xor_sync(0xffu, cv, 1);
        cv += __shfl_xor_sync(0xffu, cv, 2);
        cv += __shfl_xor_sync(0xffu, cv, 4);
        if (tid == 0) d_partials[blockIdx.x] = cv;
    }
}

// =========================================================================
// Kernel 5: deterministic final reduction -> mean loss
// =========================================================================
__global__ void finalize_k(int nblocks, int npairs, float* __restrict__ out)
{
    __shared__ float sm[256];
    float s = 0.f;
    for (int i = threadIdx.x; i < nblocks; i += 256) s += d_partials[i];
    sm[threadIdx.x] = s;
    __syncthreads();
    for (int w = 128; w > 0; w >>= 1) {
        if (threadIdx.x < w) sm[threadIdx.x] += sm[threadIdx.x + w];
        __syncthreads();
    }
    if (threadIdx.x == 0) out[0] = sm[0] / (float)npairs;
}

// =========================================================================
extern "C" void kernel_launch(void* const* d_in, const int* in_sizes, int n_in,
                              void* d_out, int out_size)
{
    const float* x        = (const float*)d_in[0];
    const float* w1       = (const float*)d_in[1];
    const float* w2       = (const float*)d_in[2];
    const int*   anchors  = (const int*)d_in[4];
    const int*   positives= (const int*)d_in[5];
    const int*   negidx   = (const int*)d_in[6];
    const int npairs = in_sizes[4];

    static int attrs_set = 0;
    if (!attrs_set) {
        cudaFuncSetAttribute(gemm1_tf32_k,
                             cudaFuncAttributeMaxDynamicSharedMemorySize, G1_SMEM_BYTES);
        cudaFuncSetAttribute(gemm2_tf32_k,
                             cudaFuncAttributeMaxDynamicSharedMemorySize, G2_SMEM_BYTES);
        cudaFuncSetAttribute(gram_k,
                             cudaFuncAttributeMaxDynamicSharedMemorySize, GRAM_SMEM_BYTES);
        attrs_set = 1;
    }

    dim3 g1(D_ / 128, B_ / 128);     // (4, 64)
    gemm1_tf32_k<<<g1, 256, G1_SMEM_BYTES>>>(x, w1);

    gemm2_tf32_k<<<B_ / 64, 256, G2_SMEM_BYTES>>>(w2);   // 128 CTAs

    dim3 gg(B_ / 128, B_ / 128);
    gram_k<<<gg, 256, GRAM_SMEM_BYTES>>>();

    int pblocks = (npairs + 255) / 256;
    gather_lse_k<<<pblocks, 256>>>(anchors, positives, negidx, npairs);

    finalize_k<<<1, 256>>>(pblocks, npairs, (float*)d_out);
}

// round 8
// speedup vs baseline: 3.3817x; 1.0074x over previous
#include <cuda_runtime.h>
#include <cuda_bf16.h>
#include <cstdint>

#define B_   8192
#define D_   512
#define PD_  128
#define NNEG 10
#define INV_SQRT_T 1.41421356237309515f   // g = h/(||h||*sqrt(T)) so g.g' = sim
#define SIM_SCALE  60.0f                  // |sim| <= 2 -> |code| <= 120 < 127
#define SIM_ISCALE (1.0f / 60.0f)

// ---------------- scratch (device globals; no allocation) ----------------
static __device__ float          d_A1[(size_t)B_ * D_];      // relu(x@w1^T), 16 MB
static __device__ __nv_bfloat16  d_g [(size_t)B_ * PD_];     // normalized h, 2 MB
static __device__ int8_t         d_sim[(size_t)B_ * B_];     // Gram int8, 67 MB
static __device__ float          d_partials[65536];
static __device__ unsigned int   d_done;

__device__ __forceinline__ uint32_t smem_addr(const void* p) {
    return (uint32_t)__cvta_generic_to_shared(p);
}
#define CP_ASYNC16(dst, src) \
    asm volatile("cp.async.cg.shared.global [%0], [%1], 16;" :: "r"(dst), "l"(src))
#define CP_COMMIT() asm volatile("cp.async.commit_group;" ::: "memory")
#define CP_WAIT1()  asm volatile("cp.async.wait_group 1;" ::: "memory")

// =========================================================================
// Kernel 1: A1 = relu(X @ W1^T) via tf32 mma.sync, cp.async double-buffered
// =========================================================================
#define TFS 36
#define G1_TILE (128 * TFS)
#define G1_SMEM_BYTES (4 * G1_TILE * 4)           // 73728 B

__global__ __launch_bounds__(256, 2)
void gemm1_tf32_k(const float* __restrict__ X, const float* __restrict__ W1)
{
    extern __shared__ uint32_t dynsm[];
    uint32_t* Asb = dynsm;
    uint32_t* Bsb = dynsm + 2 * G1_TILE;

    const int tid  = threadIdx.x;
    const int wid  = tid >> 5;
    const int lane = tid & 31;
    const int bm = blockIdx.y * 128;
    const int bn = blockIdx.x * 128;

    const int wm = (wid >> 2) * 64;
    const int wn = (wid & 3) * 32;
    const int qr = lane >> 2;
    const int qc = lane & 3;

    int srow[4], scol[4];
#pragma unroll
    for (int l = 0; l < 4; l++) {
        int id = tid + l * 256;
        srow[l] = id >> 3;
        scol[l] = (id & 7) * 4;
    }

    float acc[4][4][4];
#pragma unroll
    for (int mi = 0; mi < 4; mi++)
#pragma unroll
        for (int nj = 0; nj < 4; nj++)
#pragma unroll
            for (int q = 0; q < 4; q++) acc[mi][nj][q] = 0.f;

#pragma unroll
    for (int l = 0; l < 4; l++) {
        CP_ASYNC16(smem_addr(Asb + srow[l] * TFS + scol[l]),
                   X + (size_t)(bm + srow[l]) * D_ + scol[l]);
        CP_ASYNC16(smem_addr(Bsb + srow[l] * TFS + scol[l]),
                   W1 + (size_t)(bn + srow[l]) * D_ + scol[l]);
    }
    CP_COMMIT();

    const int NIT = D_ / 32;
    for (int it = 0; it < NIT; it++) {
        if (it + 1 < NIT) {
            int kn = (it + 1) * 32;
            uint32_t boff = ((it + 1) & 1) * G1_TILE;
#pragma unroll
            for (int l = 0; l < 4; l++) {
                CP_ASYNC16(smem_addr(Asb + boff + srow[l] * TFS + scol[l]),
                           X + (size_t)(bm + srow[l]) * D_ + kn + scol[l]);
                CP_ASYNC16(smem_addr(Bsb + boff + srow[l] * TFS + scol[l]),
                           W1 + (size_t)(bn + srow[l]) * D_ + kn + scol[l]);
            }
        }
        CP_COMMIT();
        CP_WAIT1();
        __syncthreads();

        const uint32_t* As = Asb + (it & 1) * G1_TILE;
        const uint32_t* Bs = Bsb + (it & 1) * G1_TILE;
#pragma unroll
        for (int ks = 0; ks < 4; ks++) {
            uint32_t a[4][4], b[4][2];
#pragma unroll
            for (int mi = 0; mi < 4; mi++) {
                const uint32_t* ap = As + (wm + 16 * mi + qr) * TFS + ks * 8 + qc;
                a[mi][0] = ap[0];
                a[mi][1] = ap[8 * TFS];
                a[mi][2] = ap[4];
                a[mi][3] = ap[8 * TFS + 4];
            }
#pragma unroll
            for (int nj = 0; nj < 4; nj++) {
                const uint32_t* bp = Bs + (wn + 8 * nj + qr) * TFS + ks * 8 + qc;
                b[nj][0] = bp[0];
                b[nj][1] = bp[4];
            }
#pragma unroll
            for (int mi = 0; mi < 4; mi++)
#pragma unroll
                for (int nj = 0; nj < 4; nj++)
                    asm volatile(
                        "mma.sync.aligned.m16n8k8.row.col.f32.tf32.tf32.f32 "
                        "{%0,%1,%2,%3}, {%4,%5,%6,%7}, {%8,%9}, {%0,%1,%2,%3};"
                        : "+f"(acc[mi][nj][0]), "+f"(acc[mi][nj][1]),
                          "+f"(acc[mi][nj][2]), "+f"(acc[mi][nj][3])
                        : "r"(a[mi][0]), "r"(a[mi][1]), "r"(a[mi][2]), "r"(a[mi][3]),
                          "r"(b[nj][0]), "r"(b[nj][1]));
        }
        __syncthreads();
    }

#pragma unroll
    for (int mi = 0; mi < 4; mi++)
#pragma unroll
        for (int nj = 0; nj < 4; nj++) {
            int row = bm + wm + 16 * mi + qr;
            int col = bn + wn + 8 * nj + qc * 2;
            float2 v0, v1;
            v0.x = fmaxf(acc[mi][nj][0], 0.f);
            v0.y = fmaxf(acc[mi][nj][1], 0.f);
            v1.x = fmaxf(acc[mi][nj][2], 0.f);
            v1.y = fmaxf(acc[mi][nj][3], 0.f);
            *(float2*)(d_A1 + (size_t)row * D_ + col) = v0;
            *(float2*)(d_A1 + (size_t)(row + 8) * D_ + col) = v1;
        }
}

// =========================================================================
// Kernel 2: h = A1 @ W2^T via tf32 mma.sync (cp.async), fused row-norm
// =========================================================================
#define G2_ATILE (64 * TFS)
#define G2_BTILE (128 * TFS)
#define G2_SMEM_BYTES (2 * (G2_ATILE + G2_BTILE) * 4)   // 55296 B

__global__ __launch_bounds__(256, 2)
void gemm2_tf32_k(const float* __restrict__ W2)
{
    extern __shared__ uint32_t dynsm[];
    uint32_t* Asb = dynsm;
    uint32_t* Bsb = dynsm + 2 * G2_ATILE;
    __shared__ float sqp[64][4];
    __shared__ float scale_s[64];

    const int tid  = threadIdx.x;
    const int wid  = tid >> 5;
    const int lane = tid & 31;
    const int bm = blockIdx.x * 64;

    const int wm = (wid >> 2) * 32;
    const int wn = (wid & 3) * 32;
    const int qr = lane >> 2;
    const int qc = lane & 3;

    int srow[4], scol[4];
#pragma unroll
    for (int l = 0; l < 4; l++) {
        int id = tid + l * 256;
        srow[l] = id >> 3;
        scol[l] = (id & 7) * 4;
    }

    float acc[2][4][4];
#pragma unroll
    for (int mi = 0; mi < 2; mi++)
#pragma unroll
        for (int nj = 0; nj < 4; nj++)
#pragma unroll
            for (int q = 0; q < 4; q++) acc[mi][nj][q] = 0.f;

#pragma unroll
    for (int l = 0; l < 2; l++)
        CP_ASYNC16(smem_addr(Asb + srow[l] * TFS + scol[l]),
                   d_A1 + (size_t)(bm + srow[l]) * D_ + scol[l]);
#pragma unroll
    for (int l = 0; l < 4; l++)
        CP_ASYNC16(smem_addr(Bsb + srow[l] * TFS + scol[l]),
                   W2 + (size_t)srow[l] * D_ + scol[l]);
    CP_COMMIT();

    const int NIT = D_ / 32;
    for (int it = 0; it < NIT; it++) {
        if (it + 1 < NIT) {
            int kn = (it + 1) * 32;
            uint32_t ab = ((it + 1) & 1) * G2_ATILE;
            uint32_t bb = ((it + 1) & 1) * G2_BTILE;
#pragma unroll
            for (int l = 0; l < 2; l++)
                CP_ASYNC16(smem_addr(Asb + ab + srow[l] * TFS + scol[l]),
                           d_A1 + (size_t)(bm + srow[l]) * D_ + kn + scol[l]);
#pragma unroll
            for (int l = 0; l < 4; l++)
                CP_ASYNC16(smem_addr(Bsb + bb + srow[l] * TFS + scol[l]),
                           W2 + (size_t)srow[l] * D_ + kn + scol[l]);
        }
        CP_COMMIT();
        CP_WAIT1();
        __syncthreads();

        const uint32_t* As = Asb + (it & 1) * G2_ATILE;
        const uint32_t* Bs = Bsb + (it & 1) * G2_BTILE;
#pragma unroll
        for (int ks = 0; ks < 4; ks++) {
            uint32_t a[2][4], b[4][2];
#pragma unroll
            for (int mi = 0; mi < 2; mi++) {
                const uint32_t* ap = As + (wm + 16 * mi + qr) * TFS + ks * 8 + qc;
                a[mi][0] = ap[0];
                a[mi][1] = ap[8 * TFS];
                a[mi][2] = ap[4];
                a[mi][3] = ap[8 * TFS + 4];
            }
#pragma unroll
            for (int nj = 0; nj < 4; nj++) {
                const uint32_t* bp = Bs + (wn + 8 * nj + qr) * TFS + ks * 8 + qc;
                b[nj][0] = bp[0];
                b[nj][1] = bp[4];
            }
#pragma unroll
            for (int mi = 0; mi < 2; mi++)
#pragma unroll
                for (int nj = 0; nj < 4; nj++)
                    asm volatile(
                        "mma.sync.aligned.m16n8k8.row.col.f32.tf32.tf32.f32 "
                        "{%0,%1,%2,%3}, {%4,%5,%6,%7}, {%8,%9}, {%0,%1,%2,%3};"
                        : "+f"(acc[mi][nj][0]), "+f"(acc[mi][nj][1]),
                          "+f"(acc[mi][nj][2]), "+f"(acc[mi][nj][3])
                        : "r"(a[mi][0]), "r"(a[mi][1]), "r"(a[mi][2]), "r"(a[mi][3]),
                          "r"(b[nj][0]), "r"(b[nj][1]));
        }
        __syncthreads();
    }

#pragma unroll
    for (int mi = 0; mi < 2; mi++) {
        float s0 = 0.f, s1 = 0.f;
#pragma unroll
        for (int nj = 0; nj < 4; nj++) {
            s0 = fmaf(acc[mi][nj][0], acc[mi][nj][0], s0);
            s0 = fmaf(acc[mi][nj][1], acc[mi][nj][1], s0);
            s1 = fmaf(acc[mi][nj][2], acc[mi][nj][2], s1);
            s1 = fmaf(acc[mi][nj][3], acc[mi][nj][3], s1);
        }
        s0 += __shfl_xor_sync(0xffffffffu, s0, 1);
        s0 += __shfl_xor_sync(0xffffffffu, s0, 2);
        s1 += __shfl_xor_sync(0xffffffffu, s1, 1);
        s1 += __shfl_xor_sync(0xffffffffu, s1, 2);
        if (qc == 0) {
            sqp[wm + 16 * mi + qr][wid & 3]     = s0;
            sqp[wm + 16 * mi + qr + 8][wid & 3] = s1;
        }
    }
    __syncthreads();
    if (tid < 64) {
        float ss = sqp[tid][0] + sqp[tid][1] + sqp[tid][2] + sqp[tid][3];
        scale_s[tid] = rsqrtf(fmaxf(ss, 1e-24f)) * INV_SQRT_T;
    }
    __syncthreads();

#pragma unroll
    for (int mi = 0; mi < 2; mi++)
#pragma unroll
        for (int nj = 0; nj < 4; nj++) {
            int r0 = wm + 16 * mi + qr;
            int col = wn + 8 * nj + qc * 2;
            float sc0 = scale_s[r0];
            float sc1 = scale_s[r0 + 8];
            __nv_bfloat162 lo = __floats2bfloat162_rn(acc[mi][nj][0] * sc0,
                                                      acc[mi][nj][1] * sc0);
            __nv_bfloat162 hi = __floats2bfloat162_rn(acc[mi][nj][2] * sc1,
                                                      acc[mi][nj][3] * sc1);
            *(__nv_bfloat162*)(d_g + (size_t)(bm + r0) * PD_ + col) = lo;
            *(__nv_bfloat162*)(d_g + (size_t)(bm + r0 + 8) * PD_ + col) = hi;
        }
}

// =========================================================================
// Kernel 3: Gram (UPPER TRIANGLE): int8 sim = round(g@g^T * SIM_SCALE)
// bf16 HMMA + ldmatrix; bf16 SMEM staging, int8 convert on copy-out.
// =========================================================================
#define TSTRIDE 136
#define GRAM_SMEM_BYTES (2 * 128 * TSTRIDE * 2)

__global__ __launch_bounds__(256, 2)
void gram_k()
{
    if (blockIdx.x < blockIdx.y) return;

    extern __shared__ __nv_bfloat16 smg[];
    __nv_bfloat16* As = smg;
    __nv_bfloat16* Bs = smg + 128 * TSTRIDE;

    const int tid  = threadIdx.x;
    const int wid  = tid >> 5;
    const int lane = tid & 31;
    const int m0 = blockIdx.y * 128;
    const int n0 = blockIdx.x * 128;

    const uint4* grow = (const uint4*)d_g;
#pragma unroll
    for (int i = 0; i < 8; i++) {
        int id = tid + i * 256;
        int r  = id >> 4;
        int ch = id & 15;
        uint4 va = grow[(size_t)(m0 + r) * 16 + ch];
        uint4 vb = grow[(size_t)(n0 + r) * 16 + ch];
        *(uint4*)(As + r * TSTRIDE + ch * 8) = va;
        *(uint4*)(Bs + r * TSTRIDE + ch * 8) = vb;
    }
    __syncthreads();

    const int wm = (wid >> 2) * 64;
    const int wn = (wid & 3) * 32;
    const int qr = lane >> 2;
    const int qc = (lane & 3) * 2;

    const int a_row = lane & 15;
    const int a_kof = (lane >> 4) * 8;
    const int g3    = lane >> 3;
    const int b_row = 8 * (g3 >> 1) + (lane & 7);
    const int b_kof = 8 * (g3 & 1);

    float acc[4][4][4];
#pragma unroll
    for (int mi = 0; mi < 4; mi++)
#pragma unroll
        for (int nj = 0; nj < 4; nj++)
#pragma unroll
            for (int q = 0; q < 4; q++) acc[mi][nj][q] = 0.f;

#pragma unroll
    for (int ks = 0; ks < 8; ks++) {
        uint32_t a[4][4], b[4][2];
#pragma unroll
        for (int mi = 0; mi < 4; mi++) {
            uint32_t ad = smem_addr(As + (wm + 16 * mi + a_row) * TSTRIDE
                                       + ks * 16 + a_kof);
            asm volatile("ldmatrix.sync.aligned.m8n8.x4.shared.b16 "
                         "{%0,%1,%2,%3}, [%4];"
                         : "=r"(a[mi][0]), "=r"(a[mi][1]),
                           "=r"(a[mi][2]), "=r"(a[mi][3]) : "r"(ad));
        }
#pragma unroll
        for (int nj2 = 0; nj2 < 2; nj2++) {
            uint32_t bd = smem_addr(Bs + (wn + 16 * nj2 + b_row) * TSTRIDE
                                       + ks * 16 + b_kof);
            asm volatile("ldmatrix.sync.aligned.m8n8.x4.shared.b16 "
                         "{%0,%1,%2,%3}, [%4];"
                         : "=r"(b[2 * nj2][0]), "=r"(b[2 * nj2][1]),
                           "=r"(b[2 * nj2 + 1][0]), "=r"(b[2 * nj2 + 1][1])
                         : "r"(bd));
        }
#pragma unroll
        for (int mi = 0; mi < 4; mi++)
#pragma unroll
            for (int nj = 0; nj < 4; nj++)
                asm volatile(
                    "mma.sync.aligned.m16n8k16.row.col.f32.bf16.bf16.f32 "
                    "{%0,%1,%2,%3}, {%4,%5,%6,%7}, {%8,%9}, {%0,%1,%2,%3};"
                    : "+f"(acc[mi][nj][0]), "+f"(acc[mi][nj][1]),
                      "+f"(acc[mi][nj][2]), "+f"(acc[mi][nj][3])
                    : "r"(a[mi][0]), "r"(a[mi][1]), "r"(a[mi][2]), "r"(a[mi][3]),
                      "r"(b[nj][0]), "r"(b[nj][1]));
    }

    __syncthreads();
    __nv_bfloat16* Es = As;
#pragma unroll
    for (int mi = 0; mi < 4; mi++)
#pragma unroll
        for (int nj = 0; nj < 4; nj++) {
            int r0 = wm + 16 * mi + qr;
            int c0 = wn + 8 * nj + qc;
            __nv_bfloat162 lo = __floats2bfloat162_rn(acc[mi][nj][0], acc[mi][nj][1]);
            __nv_bfloat162 hi = __floats2bfloat162_rn(acc[mi][nj][2], acc[mi][nj][3]);
            *(__nv_bfloat162*)(Es + r0 * TSTRIDE + c0) = lo;
            *(__nv_bfloat162*)(Es + (r0 + 8) * TSTRIDE + c0) = hi;
        }
    __syncthreads();

    // copy-out with bf16 -> int8 conversion; 8B stores, 128B-coalesced
#pragma unroll
    for (int i = 0; i < 8; i++) {
        int id = tid + i * 256;
        int r  = id >> 4;
        int ch = id & 15;
        const __nv_bfloat16* src = Es + r * TSTRIDE + ch * 8;
        int8_t q[8];
#pragma unroll
        for (int e = 0; e < 8; e++) {
            float v = __bfloat162float(src[e]) * SIM_SCALE;
            int iv = __float2int_rn(v);
            q[e] = (int8_t)max(-127, min(127, iv));
        }
        *(uint2*)(d_sim + (size_t)(m0 + r) * B_ + n0 + ch * 8) = *(uint2*)q;
    }
}

// =========================================================================
// Kernel 4: gather 11 int8 sims per pair + logsumexp + fused finalize
// =========================================================================
__global__ __launch_bounds__(256)
void gather_lse_k(const int* __restrict__ anchors,
                  const int* __restrict__ positives,
                  const int* __restrict__ negidx,
                  int npairs, float* __restrict__ out)
{
    const int tid = threadIdx.x;
    const int p = blockIdx.x * 256 + tid;
    const bool valid = (p < npairs);
    const int pc = valid ? p : 0;

    const int a = anchors[pc];
    int pidx = positives[pc];
    int nid[NNEG];
#pragma unroll
    for (int j = 0; j < NNEG; j++) nid[j] = negidx[(size_t)pc * NNEG + j];

    int r = min(a, pidx), c = max(a, pidx);
    float posv = (float)d_sim[(size_t)r * B_ + c] * SIM_ISCALE;
    float ln[NNEG];
#pragma unroll
    for (int j = 0; j < NNEG; j++) {
        int rr = min(a, nid[j]), cc = max(a, nid[j]);
        ln[j] = (float)d_sim[(size_t)rr * B_ + cc] * SIM_ISCALE;
    }

    float m = posv;
#pragma unroll
    for (int j = 0; j < NNEG; j++) m = fmaxf(m, ln[j]);
    float se = __expf(posv - m);
#pragma unroll
    for (int j = 0; j < NNEG; j++) se += __expf(ln[j] - m);
    float contrib = valid ? (m + __logf(se) - posv) : 0.f;

    contrib += __shfl_xor_sync(0xffffffffu, contrib, 1);
    contrib += __shfl_xor_sync(0xffffffffu, contrib, 2);
    contrib += __shfl_xor_sync(0xffffffffu, contrib, 4);
    contrib += __shfl_xor_sync(0xffffffffu, contrib, 8);
    contrib += __shfl_xor_sync(0xffffffffu, contrib, 16);
    __shared__ float ws[8];
    __shared__ int is_last;
    if ((tid & 31) == 0) ws[tid >> 5] = contrib;
    __syncthreads();
    if (tid < 8) {
        float cv = ws[tid];
        cv += __shfl_xor_sync(0xffu, cv, 1);
        cv += __shfl_xor_sync(0xffu, cv, 2);
        cv += __shfl_xor_sync(0xffu, cv, 4);
        if (tid == 0) d_partials[blockIdx.x] = cv;
    }

    // deterministic last-block finalize
    if (tid == 0) {
        __threadfence();
        unsigned t = atomicAdd(&d_done, 1u);
        is_last = (t == gridDim.x - 1);
    }
    __syncthreads();
    if (is_last) {
        __shared__ float sm[256];
        float s = 0.f;
        for (int i = tid; i < (int)gridDim.x; i += 256) s += d_partials[i];
        sm[tid] = s;
        __syncthreads();
        for (int w = 128; w > 0; w >>= 1) {
            if (tid < w) sm[tid] += sm[tid + w];
            __syncthreads();
        }
        if (tid == 0) {
            out[0] = sm[0] / (float)npairs;
            d_done = 0;               // reset for next graph replay
        }
    }
}

// =========================================================================
extern "C" void kernel_launch(void* const* d_in, const int* in_sizes, int n_in,
                              void* d_out, int out_size)
{
    const float* x        = (const float*)d_in[0];
    const float* w1       = (const float*)d_in[1];
    const float* w2       = (const float*)d_in[2];
    const int*   anchors  = (const int*)d_in[4];
    const int*   positives= (const int*)d_in[5];
    const int*   negidx   = (const int*)d_in[6];
    const int npairs = in_sizes[4];

    static int attrs_set = 0;
    if (!attrs_set) {
        cudaFuncSetAttribute(gemm1_tf32_k,
                             cudaFuncAttributeMaxDynamicSharedMemorySize, G1_SMEM_BYTES);
        cudaFuncSetAttribute(gemm2_tf32_k,
                             cudaFuncAttributeMaxDynamicSharedMemorySize, G2_SMEM_BYTES);
        cudaFuncSetAttribute(gram_k,
                             cudaFuncAttributeMaxDynamicSharedMemorySize, GRAM_SMEM_BYTES);
        attrs_set = 1;
    }

    dim3 g1(D_ / 128, B_ / 128);
    gemm1_tf32_k<<<g1, 256, G1_SMEM_BYTES>>>(x, w1);

    gemm2_tf32_k<<<B_ / 64, 256, G2_SMEM_BYTES>>>(w2);

    dim3 gg(B_ / 128, B_ / 128);
    gram_k<<<gg, 256, GRAM_SMEM_BYTES>>>();

    int pblocks = (npairs + 255) / 256;
    gather_lse_k<<<pblocks, 256>>>(anchors, positives, negidx, npairs,
                                   (float*)d_out);
}

// round 9
// speedup vs baseline: 3.6824x; 1.0889x over previous
#include <cuda_runtime.h>
#include <cuda_bf16.h>
#include <cstdint>

#define B_   8192
#define D_   512
#define PD_  128
#define NNEG 10
#define INV_SQRT_T 1.41421356237309515f   // g = h/(||h||*sqrt(T)) so g.g' = sim
#define SIM_SCALE  60.0f                  // |sim| <= 2 -> |code| <= ~121 < 127
#define SIM_ISCALE (1.0f / 60.0f)

// ---------------- scratch (device globals; no allocation) ----------------
static __device__ __nv_bfloat16  d_Xb [(size_t)B_ * D_];     // bf16 X, 8 MB
static __device__ __nv_bfloat16  d_W1b[(size_t)D_ * D_];     // bf16 W1, 0.5 MB
static __device__ __nv_bfloat16  d_W2b[(size_t)PD_ * D_];    // bf16 W2, 128 KB
static __device__ __nv_bfloat16  d_A1b[(size_t)B_ * D_];     // relu(x@w1^T), 8 MB
static __device__ __nv_bfloat16  d_g  [(size_t)B_ * PD_];    // normalized h, 2 MB
static __device__ int8_t         d_sim[(size_t)B_ * B_];     // full symmetric, 67 MB
static __device__ float          d_partials[65536];
static __device__ unsigned int   d_done;

__device__ __forceinline__ uint32_t smem_addr(const void* p) {
    return (uint32_t)__cvta_generic_to_shared(p);
}
#define CP_ASYNC16(dst, src) \
    asm volatile("cp.async.cg.shared.global [%0], [%1], 16;" :: "r"(dst), "l"(src))
#define CP_COMMIT() asm volatile("cp.async.commit_group;" ::: "memory")
#define CP_WAIT1()  asm volatile("cp.async.wait_group 1;" ::: "memory")

#define LDSM_X4(r0, r1, r2, r3, ad) \
    asm volatile("ldmatrix.sync.aligned.m8n8.x4.shared.b16 {%0,%1,%2,%3}, [%4];" \
                 : "=r"(r0), "=r"(r1), "=r"(r2), "=r"(r3) : "r"(ad))
#define MMA16816(acc, a, b) \
    asm volatile("mma.sync.aligned.m16n8k16.row.col.f32.bf16.bf16.f32 " \
                 "{%0,%1,%2,%3}, {%4,%5,%6,%7}, {%8,%9}, {%0,%1,%2,%3};" \
                 : "+f"((acc)[0]), "+f"((acc)[1]), "+f"((acc)[2]), "+f"((acc)[3]) \
                 : "r"((a)[0]), "r"((a)[1]), "r"((a)[2]), "r"((a)[3]), \
                   "r"((b)[0]), "r"((b)[1]))

// =========================================================================
// Kernel 0: fp32 -> bf16 conversion of X, W1, W2 (one pass)
// =========================================================================
#define NX4  (B_ * D_ / 4)       // 1048576
#define NW14 (D_ * D_ / 4)       // 65536
#define NW24 (PD_ * D_ / 4)      // 16384
#define NCVT (NX4 + NW14 + NW24) // 1130496

__global__ __launch_bounds__(256)
void convert_k(const float* __restrict__ X, const float* __restrict__ W1,
               const float* __restrict__ W2)
{
    int idx = blockIdx.x * 256 + threadIdx.x;
    if (idx >= NCVT) return;
    float4 v;
    __nv_bfloat16* dst;
    if (idx < NX4) {
        v = ((const float4*)X)[idx];
        dst = d_Xb + (size_t)idx * 4;
    } else if (idx < NX4 + NW14) {
        int j = idx - NX4;
        v = ((const float4*)W1)[j];
        dst = d_W1b + (size_t)j * 4;
    } else {
        int j = idx - NX4 - NW14;
        v = ((const float4*)W2)[j];
        dst = d_W2b + (size_t)j * 4;
    }
    __nv_bfloat162 p0 = __floats2bfloat162_rn(v.x, v.y);
    __nv_bfloat162 p1 = __floats2bfloat162_rn(v.z, v.w);
    uint2 o;
    o.x = *(uint32_t*)&p0;
    o.y = *(uint32_t*)&p1;
    *(uint2*)dst = o;
}

// =========================================================================
// Kernel 1: A1 = relu(X @ W1^T) bf16 HMMA + ldmatrix + cp.async (BK=64)
// 128x128 CTA tile; 8 warps (2x4), warp tile 64x32.
// =========================================================================
#define BSTR 72                         // bf16 elems per SMEM row (64 + 8 pad)
#define G1_TILEE (128 * BSTR)           // elems per tile
#define G1_SMEM_BYTES (4 * G1_TILEE * 2)  // 2 bufs x (A+B) = 73728 B

__global__ __launch_bounds__(256, 2)
void gemm1_bf16_k()
{
    extern __shared__ __nv_bfloat16 dynb[];
    __nv_bfloat16* Asb = dynb;                      // [2][128*BSTR]
    __nv_bfloat16* Bsb = dynb + 2 * G1_TILEE;

    const int tid  = threadIdx.x;
    const int wid  = tid >> 5;
    const int lane = tid & 31;
    const int bm = blockIdx.y * 128;
    const int bn = blockIdx.x * 128;

    const int wm = (wid >> 2) * 64;
    const int wn = (wid & 3) * 32;
    const int qr = lane >> 2;
    const int qc2 = (lane & 3) * 2;

    const int a_row = lane & 15;
    const int a_kof = (lane >> 4) * 8;
    const int g3    = lane >> 3;
    const int b_row = 8 * (g3 >> 1) + (lane & 7);
    const int b_kof = 8 * (g3 & 1);

    int srow[4], scol[4];
#pragma unroll
    for (int l = 0; l < 4; l++) {
        int id = tid + l * 256;          // 0..1023
        srow[l] = id >> 3;
        scol[l] = (id & 7) * 8;
    }

    float acc[4][4][4];
#pragma unroll
    for (int mi = 0; mi < 4; mi++)
#pragma unroll
        for (int nj = 0; nj < 4; nj++)
#pragma unroll
            for (int q = 0; q < 4; q++) acc[mi][nj][q] = 0.f;

#pragma unroll
    for (int l = 0; l < 4; l++) {
        CP_ASYNC16(smem_addr(Asb + srow[l] * BSTR + scol[l]),
                   d_Xb + (size_t)(bm + srow[l]) * D_ + scol[l]);
        CP_ASYNC16(smem_addr(Bsb + srow[l] * BSTR + scol[l]),
                   d_W1b + (size_t)(bn + srow[l]) * D_ + scol[l]);
    }
    CP_COMMIT();

    const int NIT = D_ / 64;             // 8
    for (int it = 0; it < NIT; it++) {
        if (it + 1 < NIT) {
            int kn = (it + 1) * 64;
            uint32_t boff = ((it + 1) & 1) * G1_TILEE;
#pragma unroll
            for (int l = 0; l < 4; l++) {
                CP_ASYNC16(smem_addr(Asb + boff + srow[l] * BSTR + scol[l]),
                           d_Xb + (size_t)(bm + srow[l]) * D_ + kn + scol[l]);
                CP_ASYNC16(smem_addr(Bsb + boff + srow[l] * BSTR + scol[l]),
                           d_W1b + (size_t)(bn + srow[l]) * D_ + kn + scol[l]);
            }
        }
        CP_COMMIT();
        CP_WAIT1();
        __syncthreads();

        const __nv_bfloat16* As = Asb + (it & 1) * G1_TILEE;
        const __nv_bfloat16* Bs = Bsb + (it & 1) * G1_TILEE;
#pragma unroll
        for (int ks = 0; ks < 4; ks++) {
            uint32_t a[4][4], b[4][2];
#pragma unroll
            for (int mi = 0; mi < 4; mi++) {
                uint32_t ad = smem_addr(As + (wm + 16 * mi + a_row) * BSTR
                                           + ks * 16 + a_kof);
                LDSM_X4(a[mi][0], a[mi][1], a[mi][2], a[mi][3], ad);
            }
#pragma unroll
            for (int nj2 = 0; nj2 < 2; nj2++) {
                uint32_t bd = smem_addr(Bs + (wn + 16 * nj2 + b_row) * BSTR
                                           + ks * 16 + b_kof);
                LDSM_X4(b[2 * nj2][0], b[2 * nj2][1],
                        b[2 * nj2 + 1][0], b[2 * nj2 + 1][1], bd);
            }
#pragma unroll
            for (int mi = 0; mi < 4; mi++)
#pragma unroll
                for (int nj = 0; nj < 4; nj++)
                    MMA16816(acc[mi][nj], a[mi], b[nj]);
        }
        __syncthreads();
    }

    // epilogue: relu -> bf16 store
#pragma unroll
    for (int mi = 0; mi < 4; mi++)
#pragma unroll
        for (int nj = 0; nj < 4; nj++) {
            int row = bm + wm + 16 * mi + qr;
            int col = bn + wn + 8 * nj + qc2;
            __nv_bfloat162 lo = __floats2bfloat162_rn(fmaxf(acc[mi][nj][0], 0.f),
                                                      fmaxf(acc[mi][nj][1], 0.f));
            __nv_bfloat162 hi = __floats2bfloat162_rn(fmaxf(acc[mi][nj][2], 0.f),
                                                      fmaxf(acc[mi][nj][3], 0.f));
            *(__nv_bfloat162*)(d_A1b + (size_t)row * D_ + col) = lo;
            *(__nv_bfloat162*)(d_A1b + (size_t)(row + 8) * D_ + col) = hi;
        }
}

// =========================================================================
// Kernel 2: h = A1 @ W2^T bf16 HMMA + ldmatrix + cp.async, fused row-norm
// 64x128 CTA tile; 8 warps (2x4), warp tile 32x32.
// =========================================================================
#define G2_ATILEE (64 * BSTR)
#define G2_BTILEE (128 * BSTR)
#define G2_SMEM_BYTES (2 * (G2_ATILEE + G2_BTILEE) * 2)   // 55296 B

__global__ __launch_bounds__(256, 2)
void gemm2_bf16_k()
{
    extern __shared__ __nv_bfloat16 dynb[];
    __nv_bfloat16* Asb = dynb;
    __nv_bfloat16* Bsb = dynb + 2 * G2_ATILEE;
    __shared__ float sqp[64][4];
    __shared__ float scale_s[64];

    const int tid  = threadIdx.x;
    const int wid  = tid >> 5;
    const int lane = tid & 31;
    const int bm = blockIdx.x * 64;

    const int wm = (wid >> 2) * 32;
    const int wn = (wid & 3) * 32;
    const int qr = lane >> 2;
    const int qc2 = (lane & 3) * 2;

    const int a_row = lane & 15;
    const int a_kof = (lane >> 4) * 8;
    const int g3    = lane >> 3;
    const int b_row = 8 * (g3 >> 1) + (lane & 7);
    const int b_kof = 8 * (g3 & 1);

    int srow[4], scol[4];
#pragma unroll
    for (int l = 0; l < 4; l++) {
        int id = tid + l * 256;
        srow[l] = id >> 3;
        scol[l] = (id & 7) * 8;
    }

    float acc[2][4][4];
#pragma unroll
    for (int mi = 0; mi < 2; mi++)
#pragma unroll
        for (int nj = 0; nj < 4; nj++)
#pragma unroll
            for (int q = 0; q < 4; q++) acc[mi][nj][q] = 0.f;

#pragma unroll
    for (int l = 0; l < 2; l++)
        CP_ASYNC16(smem_addr(Asb + srow[l] * BSTR + scol[l]),
                   d_A1b + (size_t)(bm + srow[l]) * D_ + scol[l]);
#pragma unroll
    for (int l = 0; l < 4; l++)
        CP_ASYNC16(smem_addr(Bsb + srow[l] * BSTR + scol[l]),
                   d_W2b + (size_t)srow[l] * D_ + scol[l]);
    CP_COMMIT();

    const int NIT = D_ / 64;
    for (int it = 0; it < NIT; it++) {
        if (it + 1 < NIT) {
            int kn = (it + 1) * 64;
            uint32_t ab = ((it + 1) & 1) * G2_ATILEE;
            uint32_t bb = ((it + 1) & 1) * G2_BTILEE;
#pragma unroll
            for (int l = 0; l < 2; l++)
                CP_ASYNC16(smem_addr(Asb + ab + srow[l] * BSTR + scol[l]),
                           d_A1b + (size_t)(bm + srow[l]) * D_ + kn + scol[l]);
#pragma unroll
            for (int l = 0; l < 4; l++)
                CP_ASYNC16(smem_addr(Bsb + bb + srow[l] * BSTR + scol[l]),
                           d_W2b + (size_t)srow[l] * D_ + kn + scol[l]);
        }
        CP_COMMIT();
        CP_WAIT1();
        __syncthreads();

        const __nv_bfloat16* As = Asb + (it & 1) * G2_ATILEE;
        const __nv_bfloat16* Bs = Bsb + (it & 1) * G2_BTILEE;
#pragma unroll
        for (int ks = 0; ks < 4; ks++) {
            uint32_t a[2][4], b[4][2];
#pragma unroll
            for (int mi = 0; mi < 2; mi++) {
                uint32_t ad = smem_addr(As + (wm + 16 * mi + a_row) * BSTR
                                           + ks * 16 + a_kof);
                LDSM_X4(a[mi][0], a[mi][1], a[mi][2], a[mi][3], ad);
            }
#pragma unroll
            for (int nj2 = 0; nj2 < 2; nj2++) {
                uint32_t bd = smem_addr(Bs + (wn + 16 * nj2 + b_row) * BSTR
                                           + ks * 16 + b_kof);
                LDSM_X4(b[2 * nj2][0], b[2 * nj2][1],
                        b[2 * nj2 + 1][0], b[2 * nj2 + 1][1], bd);
            }
#pragma unroll
            for (int mi = 0; mi < 2; mi++)
#pragma unroll
                for (int nj = 0; nj < 4; nj++)
                    MMA16816(acc[mi][nj], a[mi], b[nj]);
        }
        __syncthreads();
    }

    // fused row-norm
#pragma unroll
    for (int mi = 0; mi < 2; mi++) {
        float s0 = 0.f, s1 = 0.f;
#pragma unroll
        for (int nj = 0; nj < 4; nj++) {
            s0 = fmaf(acc[mi][nj][0], acc[mi][nj][0], s0);
            s0 = fmaf(acc[mi][nj][1], acc[mi][nj][1], s0);
            s1 = fmaf(acc[mi][nj][2], acc[mi][nj][2], s1);
            s1 = fmaf(acc[mi][nj][3], acc[mi][nj][3], s1);
        }
        s0 += __shfl_xor_sync(0xffffffffu, s0, 1);
        s0 += __shfl_xor_sync(0xffffffffu, s0, 2);
        s1 += __shfl_xor_sync(0xffffffffu, s1, 1);
        s1 += __shfl_xor_sync(0xffffffffu, s1, 2);
        if ((lane & 3) == 0) {
            sqp[wm + 16 * mi + qr][wid & 3]     = s0;
            sqp[wm + 16 * mi + qr + 8][wid & 3] = s1;
        }
    }
    __syncthreads();
    if (tid < 64) {
        float ss = sqp[tid][0] + sqp[tid][1] + sqp[tid][2] + sqp[tid][3];
        scale_s[tid] = rsqrtf(fmaxf(ss, 1e-24f)) * INV_SQRT_T;
    }
    __syncthreads();

#pragma unroll
    for (int mi = 0; mi < 2; mi++)
#pragma unroll
        for (int nj = 0; nj < 4; nj++) {
            int r0 = wm + 16 * mi + qr;
            int col = wn + 8 * nj + qc2;
            float sc0 = scale_s[r0];
            float sc1 = scale_s[r0 + 8];
            __nv_bfloat162 lo = __floats2bfloat162_rn(acc[mi][nj][0] * sc0,
                                                      acc[mi][nj][1] * sc0);
            __nv_bfloat162 hi = __floats2bfloat162_rn(acc[mi][nj][2] * sc1,
                                                      acc[mi][nj][3] * sc1);
            *(__nv_bfloat162*)(d_g + (size_t)(bm + r0) * PD_ + col) = lo;
            *(__nv_bfloat162*)(d_g + (size_t)(bm + r0 + 8) * PD_ + col) = hi;
        }
}

// =========================================================================
// Kernel 3: Gram: int8 sim = round(g@g^T * SIM_SCALE), SYMMETRIC store.
// Upper tiles computed; each off-diagonal tile also written transposed.
// =========================================================================
#define TSTRIDE 136
#define GRAM_SMEM_BYTES (2 * 128 * TSTRIDE * 2)

__global__ __launch_bounds__(256, 2)
void gram_k()
{
    if (blockIdx.x < blockIdx.y) return;

    extern __shared__ __nv_bfloat16 smg[];
    __nv_bfloat16* As = smg;
    __nv_bfloat16* Bs = smg + 128 * TSTRIDE;

    const int tid  = threadIdx.x;
    const int wid  = tid >> 5;
    const int lane = tid & 31;
    const int m0 = blockIdx.y * 128;
    const int n0 = blockIdx.x * 128;

    const uint4* grow = (const uint4*)d_g;
#pragma unroll
    for (int i = 0; i < 8; i++) {
        int id = tid + i * 256;
        int r  = id >> 4;
        int ch = id & 15;
        uint4 va = grow[(size_t)(m0 + r) * 16 + ch];
        uint4 vb = grow[(size_t)(n0 + r) * 16 + ch];
        *(uint4*)(As + r * TSTRIDE + ch * 8) = va;
        *(uint4*)(Bs + r * TSTRIDE + ch * 8) = vb;
    }
    __syncthreads();

    const int wm = (wid >> 2) * 64;
    const int wn = (wid & 3) * 32;
    const int qr = lane >> 2;
    const int qc = (lane & 3) * 2;

    const int a_row = lane & 15;
    const int a_kof = (lane >> 4) * 8;
    const int g3    = lane >> 3;
    const int b_row = 8 * (g3 >> 1) + (lane & 7);
    const int b_kof = 8 * (g3 & 1);

    float acc[4][4][4];
#pragma unroll
    for (int mi = 0; mi < 4; mi++)
#pragma unroll
        for (int nj = 0; nj < 4; nj++)
#pragma unroll
            for (int q = 0; q < 4; q++) acc[mi][nj][q] = 0.f;

#pragma unroll
    for (int ks = 0; ks < 8; ks++) {
        uint32_t a[4][4], b[4][2];
#pragma unroll
        for (int mi = 0; mi < 4; mi++) {
            uint32_t ad = smem_addr(As + (wm + 16 * mi + a_row) * TSTRIDE
                                       + ks * 16 + a_kof);
            LDSM_X4(a[mi][0], a[mi][1], a[mi][2], a[mi][3], ad);
        }
#pragma unroll
        for (int nj2 = 0; nj2 < 2; nj2++) {
            uint32_t bd = smem_addr(Bs + (wn + 16 * nj2 + b_row) * TSTRIDE
                                       + ks * 16 + b_kof);
            LDSM_X4(b[2 * nj2][0], b[2 * nj2][1],
                    b[2 * nj2 + 1][0], b[2 * nj2 + 1][1], bd);
        }
#pragma unroll
        for (int mi = 0; mi < 4; mi++)
#pragma unroll
            for (int nj = 0; nj < 4; nj++)
                MMA16816(acc[mi][nj], a[mi], b[nj]);
    }

    // ---- primary (m0, n0) tile: bf16 stage -> int8 copy-out ----
    __syncthreads();
    __nv_bfloat16* Es = As;
#pragma unroll
    for (int mi = 0; mi < 4; mi++)
#pragma unroll
        for (int nj = 0; nj < 4; nj++) {
            int r0 = wm + 16 * mi + qr;
            int c0 = wn + 8 * nj + qc;
            __nv_bfloat162 lo = __floats2bfloat162_rn(acc[mi][nj][0], acc[mi][nj][1]);
            __nv_bfloat162 hi = __floats2bfloat162_rn(acc[mi][nj][2], acc[mi][nj][3]);
            *(__nv_bfloat162*)(Es + r0 * TSTRIDE + c0) = lo;
            *(__nv_bfloat162*)(Es + (r0 + 8) * TSTRIDE + c0) = hi;
        }
    __syncthreads();

#pragma unroll
    for (int i = 0; i < 8; i++) {
        int id = tid + i * 256;
        int r  = id >> 4;
        int ch = id & 15;
        const __nv_bfloat16* src = Es + r * TSTRIDE + ch * 8;
        int8_t q[8];
#pragma unroll
        for (int e = 0; e < 8; e++) {
            int iv = __float2int_rn(__bfloat162float(src[e]) * SIM_SCALE);
            q[e] = (int8_t)max(-127, min(127, iv));
        }
        *(uint2*)(d_sim + (size_t)(m0 + r) * B_ + n0 + ch * 8) = *(uint2*)q;
    }

    // ---- mirror (n0, m0) tile: transposed restage -> int8 copy-out ----
    if (blockIdx.x != blockIdx.y) {
        __syncthreads();
#pragma unroll
        for (int mi = 0; mi < 4; mi++)
#pragma unroll
            for (int nj = 0; nj < 4; nj++) {
                int r0 = wm + 16 * mi + qr;
                int c0 = wn + 8 * nj + qc;
                Es[c0 * TSTRIDE + r0]           = __float2bfloat16(acc[mi][nj][0]);
                Es[(c0 + 1) * TSTRIDE + r0]     = __float2bfloat16(acc[mi][nj][1]);
                Es[c0 * TSTRIDE + r0 + 8]       = __float2bfloat16(acc[mi][nj][2]);
                Es[(c0 + 1) * TSTRIDE + r0 + 8] = __float2bfloat16(acc[mi][nj][3]);
            }
        __syncthreads();

#pragma unroll
        for (int i = 0; i < 8; i++) {
            int id = tid + i * 256;
            int r  = id >> 4;
            int ch = id & 15;
            const __nv_bfloat16* src = Es + r * TSTRIDE + ch * 8;
            int8_t q[8];
#pragma unroll
            for (int e = 0; e < 8; e++) {
                int iv = __float2int_rn(__bfloat162float(src[e]) * SIM_SCALE);
                q[e] = (int8_t)max(-127, min(127, iv));
            }
            *(uint2*)(d_sim + (size_t)(n0 + r) * B_ + m0 + ch * 8) = *(uint2*)q;
        }
    }
}

// =========================================================================
// Kernel 4: row-local gather + logsumexp + fused deterministic finalize
// =========================================================================
__global__ __launch_bounds__(256)
void gather_lse_k(const int* __restrict__ anchors,
                  const int* __restrict__ positives,
                  const int* __restrict__ negidx,
                  int npairs, float* __restrict__ out)
{
    const int tid = threadIdx.x;
    const int p = blockIdx.x * 256 + tid;
    const bool valid = (p < npairs);
    const int pc = valid ? p : 0;

    const int a = anchors[pc];
    const int8_t* __restrict__ row = d_sim + (size_t)a * B_;
    int pidx = positives[pc];
    int nid[NNEG];
#pragma unroll
    for (int j = 0; j < NNEG; j++) nid[j] = negidx[(size_t)pc * NNEG + j];

    float posv = (float)row[pidx] * SIM_ISCALE;
    float ln[NNEG];
#pragma unroll
    for (int j = 0; j < NNEG; j++) ln[j] = (float)row[nid[j]] * SIM_ISCALE;

    float m = posv;
#pragma unroll
    for (int j = 0; j < NNEG; j++) m = fmaxf(m, ln[j]);
    float se = __expf(posv - m);
#pragma unroll
    for (int j = 0; j < NNEG; j++) se += __expf(ln[j] - m);
    float contrib = valid ? (m + __logf(se) - posv) : 0.f;

    contrib += __shfl_xor_sync(0xffffffffu, contrib, 1);
    contrib += __shfl_xor_sync(0xffffffffu, contrib, 2);
    contrib += __shfl_xor_sync(0xffffffffu, contrib, 4);
    contrib += __shfl_xor_sync(0xffffffffu, contrib, 8);
    contrib += __shfl_xor_sync(0xffffffffu, contrib, 16);
    __shared__ float ws[8];
    __shared__ int is_last;
    if ((tid & 31) == 0) ws[tid >> 5] = contrib;
    __syncthreads();
    if (tid < 8) {
        float cv = ws[tid];
        cv += __shfl_xor_sync(0xffu, cv, 1);
        cv += __shfl_xor_sync(0xffu, cv, 2);
        cv += __shfl_xor_sync(0xffu, cv, 4);
        if (tid == 0) d_partials[blockIdx.x] = cv;
    }

    if (tid == 0) {
        __threadfence();
        unsigned t = atomicAdd(&d_done, 1u);
        is_last = (t == gridDim.x - 1);
    }
    __syncthreads();
    if (is_last) {
        __shared__ float sm[256];
        float s = 0.f;
        for (int i = tid; i < (int)gridDim.x; i += 256) s += d_partials[i];
        sm[tid] = s;
        __syncthreads();
        for (int w = 128; w > 0; w >>= 1) {
            if (tid < w) sm[tid] += sm[tid + w];
            __syncthreads();
        }
        if (tid == 0) {
            out[0] = sm[0] / (float)npairs;
            d_done = 0;
        }
    }
}

// =========================================================================
extern "C" void kernel_launch(void* const* d_in, const int* in_sizes, int n_in,
                              void* d_out, int out_size)
{
    const float* x        = (const float*)d_in[0];
    const float* w1       = (const float*)d_in[1];
    const float* w2       = (const float*)d_in[2];
    const int*   anchors  = (const int*)d_in[4];
    const int*   positives= (const int*)d_in[5];
    const int*   negidx   = (const int*)d_in[6];
    const int npairs = in_sizes[4];

    static int attrs_set = 0;
    if (!attrs_set) {
        cudaFuncSetAttribute(gemm1_bf16_k,
                             cudaFuncAttributeMaxDynamicSharedMemorySize, G1_SMEM_BYTES);
        cudaFuncSetAttribute(gemm2_bf16_k,
                             cudaFuncAttributeMaxDynamicSharedMemorySize, G2_SMEM_BYTES);
        cudaFuncSetAttribute(gram_k,
                             cudaFuncAttributeMaxDynamicSharedMemorySize, GRAM_SMEM_BYTES);
        attrs_set = 1;
    }

    convert_k<<<(NCVT + 255) / 256, 256>>>(x, w1, w2);

    dim3 g1(D_ / 128, B_ / 128);          // (4, 64)
    gemm1_bf16_k<<<g1, 256, G1_SMEM_BYTES>>>();

    gemm2_bf16_k<<<B_ / 64, 256, G2_SMEM_BYTES>>>();

    dim3 gg(B_ / 128, B_ / 128);
    gram_k<<<gg, 256, GRAM_SMEM_BYTES>>>();

    int pblocks = (npairs + 255) / 256;
    gather_lse_k<<<pblocks, 256>>>(anchors, positives, negidx, npairs,
                                   (float*)d_out);
}

// round 10
// speedup vs baseline: 4.0579x; 1.1020x over previous
#include <cuda_runtime.h>
#include <cuda_bf16.h>
#include <cstdint>

#define B_   8192
#define D_   512
#define PD_  128
#define NNEG 10
#define INV_SQRT_T 1.41421356237309515f   // g = h/(||h||*sqrt(T)) so g.g' = sim
#define SIM_SCALE  60.0f                  // |sim| <= 2 -> |code| <= ~121 < 127
#define SIM_ISCALE (1.0f / 60.0f)

// ---------------- scratch (device globals; no allocation) ----------------
static __device__ __nv_bfloat16  d_Xb [(size_t)B_ * D_];     // bf16 X, 8 MB
static __device__ __nv_bfloat16  d_W1b[(size_t)D_ * D_];     // bf16 W1, 0.5 MB
static __device__ __nv_bfloat16  d_W2b[(size_t)PD_ * D_];    // bf16 W2, 128 KB
static __device__ __nv_bfloat16  d_A1b[(size_t)B_ * D_];     // relu(x@w1^T), 8 MB
static __device__ __nv_bfloat16  d_g  [(size_t)B_ * PD_];    // normalized h, 2 MB
static __device__ int8_t         d_sim[(size_t)B_ * B_];     // full symmetric, 67 MB
static __device__ float          d_partials[65536];
static __device__ unsigned int   d_done;

__device__ __forceinline__ uint32_t smem_addr(const void* p) {
    return (uint32_t)__cvta_generic_to_shared(p);
}
#define CP_ASYNC16(dst, src) \
    asm volatile("cp.async.cg.shared.global [%0], [%1], 16;" :: "r"(dst), "l"(src))
#define CP_COMMIT() asm volatile("cp.async.commit_group;" ::: "memory")
#define CP_WAIT1()  asm volatile("cp.async.wait_group 1;" ::: "memory")

#define LDSM_X4(r0, r1, r2, r3, ad) \
    asm volatile("ldmatrix.sync.aligned.m8n8.x4.shared.b16 {%0,%1,%2,%3}, [%4];" \
                 : "=r"(r0), "=r"(r1), "=r"(r2), "=r"(r3) : "r"(ad))
#define MMA16816(acc, a, b) \
    asm volatile("mma.sync.aligned.m16n8k16.row.col.f32.bf16.bf16.f32 " \
                 "{%0,%1,%2,%3}, {%4,%5,%6,%7}, {%8,%9}, {%0,%1,%2,%3};" \
                 : "+f"((acc)[0]), "+f"((acc)[1]), "+f"((acc)[2]), "+f"((acc)[3]) \
                 : "r"((a)[0]), "r"((a)[1]), "r"((a)[2]), "r"((b)[0]), "r"((b)[1]))

// fix macro above: need all 4 a regs — define properly below
#undef MMA16816
#define MMA16816(acc, a, b) \
    asm volatile("mma.sync.aligned.m16n8k16.row.col.f32.bf16.bf16.f32 " \
                 "{%0,%1,%2,%3}, {%4,%5,%6,%7}, {%8,%9}, {%0,%1,%2,%3};" \
                 : "+f"((acc)[0]), "+f"((acc)[1]), "+f"((acc)[2]), "+f"((acc)[3]) \
                 : "r"((a)[0]), "r"((a)[1]), "r"((a)[2]), "r"((a)[3]), \
                   "r"((b)[0]), "r"((b)[1]))

// quantize 2 floats -> packed s8 pair in low 16 bits (byte0 = f0, byte1 = f1)
__device__ __forceinline__ uint32_t pack2_s8(float f0, float f1)
{
    int i0 = __float2int_rn(f0);
    int i1 = __float2int_rn(f1);
    uint32_t r;
    asm("cvt.pack.sat.s8.s32.b32 %0, %1, %2, 0;" : "=r"(r) : "r"(i1), "r"(i0));
    return r;
}

// =========================================================================
// Kernel 0: fp32 -> bf16 conversion of X, W1, W2 (one pass)
// =========================================================================
#define NX4  (B_ * D_ / 4)
#define NW14 (D_ * D_ / 4)
#define NW24 (PD_ * D_ / 4)
#define NCVT (NX4 + NW14 + NW24)

__global__ __launch_bounds__(256)
void convert_k(const float* __restrict__ X, const float* __restrict__ W1,
               const float* __restrict__ W2)
{
    int idx = blockIdx.x * 256 + threadIdx.x;
    if (idx >= NCVT) return;
    float4 v;
    __nv_bfloat16* dst;
    if (idx < NX4) {
        v = ((const float4*)X)[idx];
        dst = d_Xb + (size_t)idx * 4;
    } else if (idx < NX4 + NW14) {
        int j = idx - NX4;
        v = ((const float4*)W1)[j];
        dst = d_W1b + (size_t)j * 4;
    } else {
        int j = idx - NX4 - NW14;
        v = ((const float4*)W2)[j];
        dst = d_W2b + (size_t)j * 4;
    }
    __nv_bfloat162 p0 = __floats2bfloat162_rn(v.x, v.y);
    __nv_bfloat162 p1 = __floats2bfloat162_rn(v.z, v.w);
    uint2 o;
    o.x = *(uint32_t*)&p0;
    o.y = *(uint32_t*)&p1;
    *(uint2*)dst = o;
}

// =========================================================================
// Kernel 1: A1 = relu(X @ W1^T) bf16 HMMA + ldmatrix + cp.async (BK=64)
// =========================================================================
#define BSTR 72
#define G1_TILEE (128 * BSTR)
#define G1_SMEM_BYTES (4 * G1_TILEE * 2)

__global__ __launch_bounds__(256, 2)
void gemm1_bf16_k()
{
    extern __shared__ __nv_bfloat16 dynb[];
    __nv_bfloat16* Asb = dynb;
    __nv_bfloat16* Bsb = dynb + 2 * G1_TILEE;

    const int tid  = threadIdx.x;
    const int wid  = tid >> 5;
    const int lane = tid & 31;
    const int bm = blockIdx.y * 128;
    const int bn = blockIdx.x * 128;

    const int wm = (wid >> 2) * 64;
    const int wn = (wid & 3) * 32;
    const int qr = lane >> 2;
    const int qc2 = (lane & 3) * 2;

    const int a_row = lane & 15;
    const int a_kof = (lane >> 4) * 8;
    const int g3    = lane >> 3;
    const int b_row = 8 * (g3 >> 1) + (lane & 7);
    const int b_kof = 8 * (g3 & 1);

    int srow[4], scol[4];
#pragma unroll
    for (int l = 0; l < 4; l++) {
        int id = tid + l * 256;
        srow[l] = id >> 3;
        scol[l] = (id & 7) * 8;
    }

    float acc[4][4][4];
#pragma unroll
    for (int mi = 0; mi < 4; mi++)
#pragma unroll
        for (int nj = 0; nj < 4; nj++)
#pragma unroll
            for (int q = 0; q < 4; q++) acc[mi][nj][q] = 0.f;

#pragma unroll
    for (int l = 0; l < 4; l++) {
        CP_ASYNC16(smem_addr(Asb + srow[l] * BSTR + scol[l]),
                   d_Xb + (size_t)(bm + srow[l]) * D_ + scol[l]);
        CP_ASYNC16(smem_addr(Bsb + srow[l] * BSTR + scol[l]),
                   d_W1b + (size_t)(bn + srow[l]) * D_ + scol[l]);
    }
    CP_COMMIT();

    const int NIT = D_ / 64;
    for (int it = 0; it < NIT; it++) {
        if (it + 1 < NIT) {
            int kn = (it + 1) * 64;
            uint32_t boff = ((it + 1) & 1) * G1_TILEE;
#pragma unroll
            for (int l = 0; l < 4; l++) {
                CP_ASYNC16(smem_addr(Asb + boff + srow[l] * BSTR + scol[l]),
                           d_Xb + (size_t)(bm + srow[l]) * D_ + kn + scol[l]);
                CP_ASYNC16(smem_addr(Bsb + boff + srow[l] * BSTR + scol[l]),
                           d_W1b + (size_t)(bn + srow[l]) * D_ + kn + scol[l]);
            }
        }
        CP_COMMIT();
        CP_WAIT1();
        __syncthreads();

        const __nv_bfloat16* As = Asb + (it & 1) * G1_TILEE;
        const __nv_bfloat16* Bs = Bsb + (it & 1) * G1_TILEE;
#pragma unroll
        for (int ks = 0; ks < 4; ks++) {
            uint32_t a[4][4], b[4][2];
#pragma unroll
            for (int mi = 0; mi < 4; mi++) {
                uint32_t ad = smem_addr(As + (wm + 16 * mi + a_row) * BSTR
                                           + ks * 16 + a_kof);
                LDSM_X4(a[mi][0], a[mi][1], a[mi][2], a[mi][3], ad);
            }
#pragma unroll
            for (int nj2 = 0; nj2 < 2; nj2++) {
                uint32_t bd = smem_addr(Bs + (wn + 16 * nj2 + b_row) * BSTR
                                           + ks * 16 + b_kof);
                LDSM_X4(b[2 * nj2][0], b[2 * nj2][1],
                        b[2 * nj2 + 1][0], b[2 * nj2 + 1][1], bd);
            }
#pragma unroll
            for (int mi = 0; mi < 4; mi++)
#pragma unroll
                for (int nj = 0; nj < 4; nj++)
                    MMA16816(acc[mi][nj], a[mi], b[nj]);
        }
        __syncthreads();
    }

#pragma unroll
    for (int mi = 0; mi < 4; mi++)
#pragma unroll
        for (int nj = 0; nj < 4; nj++) {
            int row = bm + wm + 16 * mi + qr;
            int col = bn + wn + 8 * nj + qc2;
            __nv_bfloat162 lo = __floats2bfloat162_rn(fmaxf(acc[mi][nj][0], 0.f),
                                                      fmaxf(acc[mi][nj][1], 0.f));
            __nv_bfloat162 hi = __floats2bfloat162_rn(fmaxf(acc[mi][nj][2], 0.f),
                                                      fmaxf(acc[mi][nj][3], 0.f));
            *(__nv_bfloat162*)(d_A1b + (size_t)row * D_ + col) = lo;
            *(__nv_bfloat162*)(d_A1b + (size_t)(row + 8) * D_ + col) = hi;
        }
}

// =========================================================================
// Kernel 2: h = A1 @ W2^T bf16 HMMA + ldmatrix + cp.async, fused row-norm
// =========================================================================
#define G2_ATILEE (64 * BSTR)
#define G2_BTILEE (128 * BSTR)
#define G2_SMEM_BYTES (2 * (G2_ATILEE + G2_BTILEE) * 2)

__global__ __launch_bounds__(256, 2)
void gemm2_bf16_k()
{
    extern __shared__ __nv_bfloat16 dynb[];
    __nv_bfloat16* Asb = dynb;
    __nv_bfloat16* Bsb = dynb + 2 * G2_ATILEE;
    __shared__ float sqp[64][4];
    __shared__ float scale_s[64];

    const int tid  = threadIdx.x;
    const int wid  = tid >> 5;
    const int lane = tid & 31;
    const int bm = blockIdx.x * 64;

    const int wm = (wid >> 2) * 32;
    const int wn = (wid & 3) * 32;
    const int qr = lane >> 2;
    const int qc2 = (lane & 3) * 2;

    const int a_row = lane & 15;
    const int a_kof = (lane >> 4) * 8;
    const int g3    = lane >> 3;
    const int b_row = 8 * (g3 >> 1) + (lane & 7);
    const int b_kof = 8 * (g3 & 1);

    int srow[4], scol[4];
#pragma unroll
    for (int l = 0; l < 4; l++) {
        int id = tid + l * 256;
        srow[l] = id >> 3;
        scol[l] = (id & 7) * 8;
    }

    float acc[2][4][4];
#pragma unroll
    for (int mi = 0; mi < 2; mi++)
#pragma unroll
        for (int nj = 0; nj < 4; nj++)
#pragma unroll
            for (int q = 0; q < 4; q++) acc[mi][nj][q] = 0.f;

#pragma unroll
    for (int l = 0; l < 2; l++)
        CP_ASYNC16(smem_addr(Asb + srow[l] * BSTR + scol[l]),
                   d_A1b + (size_t)(bm + srow[l]) * D_ + scol[l]);
#pragma unroll
    for (int l = 0; l < 4; l++)
        CP_ASYNC16(smem_addr(Bsb + srow[l] * BSTR + scol[l]),
                   d_W2b + (size_t)srow[l] * D_ + scol[l]);
    CP_COMMIT();

    const int NIT = D_ / 64;
    for (int it = 0; it < NIT; it++) {
        if (it + 1 < NIT) {
            int kn = (it + 1) * 64;
            uint32_t ab = ((it + 1) & 1) * G2_ATILEE;
            uint32_t bb = ((it + 1) & 1) * G2_BTILEE;
#pragma unroll
            for (int l = 0; l < 2; l++)
                CP_ASYNC16(smem_addr(Asb + ab + srow[l] * BSTR + scol[l]),
                           d_A1b + (size_t)(bm + srow[l]) * D_ + kn + scol[l]);
#pragma unroll
            for (int l = 0; l < 4; l++)
                CP_ASYNC16(smem_addr(Bsb + bb + srow[l] * BSTR + scol[l]),
                           d_W2b + (size_t)srow[l] * D_ + kn + scol[l]);
        }
        CP_COMMIT();
        CP_WAIT1();
        __syncthreads();

        const __nv_bfloat16* As = Asb + (it & 1) * G2_ATILEE;
        const __nv_bfloat16* Bs = Bsb + (it & 1) * G2_BTILEE;
#pragma unroll
        for (int ks = 0; ks < 4; ks++) {
            uint32_t a[2][4], b[4][2];
#pragma unroll
            for (int mi = 0; mi < 2; mi++) {
                uint32_t ad = smem_addr(As + (wm + 16 * mi + a_row) * BSTR
                                           + ks * 16 + a_kof);
                LDSM_X4(a[mi][0], a[mi][1], a[mi][2], a[mi][3], ad);
            }
#pragma unroll
            for (int nj2 = 0; nj2 < 2; nj2++) {
                uint32_t bd = smem_addr(Bs + (wn + 16 * nj2 + b_row) * BSTR
                                           + ks * 16 + b_kof);
                LDSM_X4(b[2 * nj2][0], b[2 * nj2][1],
                        b[2 * nj2 + 1][0], b[2 * nj2 + 1][1], bd);
            }
#pragma unroll
            for (int mi = 0; mi < 2; mi++)
#pragma unroll
                for (int nj = 0; nj < 4; nj++)
                    MMA16816(acc[mi][nj], a[mi], b[nj]);
        }
        __syncthreads();
    }

#pragma unroll
    for (int mi = 0; mi < 2; mi++) {
        float s0 = 0.f, s1 = 0.f;
#pragma unroll
        for (int nj = 0; nj < 4; nj++) {
            s0 = fmaf(acc[mi][nj][0], acc[mi][nj][0], s0);
            s0 = fmaf(acc[mi][nj][1], acc[mi][nj][1], s0);
            s1 = fmaf(acc[mi][nj][2], acc[mi][nj][2], s1);
            s1 = fmaf(acc[mi][nj][3], acc[mi][nj][3], s1);
        }
        s0 += __shfl_xor_sync(0xffffffffu, s0, 1);
        s0 += __shfl_xor_sync(0xffffffffu, s0, 2);
        s1 += __shfl_xor_sync(0xffffffffu, s1, 1);
        s1 += __shfl_xor_sync(0xffffffffu, s1, 2);
        if ((lane & 3) == 0) {
            sqp[wm + 16 * mi + qr][wid & 3]     = s0;
            sqp[wm + 16 * mi + qr + 8][wid & 3] = s1;
        }
    }
    __syncthreads();
    if (tid < 64) {
        float ss = sqp[tid][0] + sqp[tid][1] + sqp[tid][2] + sqp[tid][3];
        scale_s[tid] = rsqrtf(fmaxf(ss, 1e-24f)) * INV_SQRT_T;
    }
    __syncthreads();

#pragma unroll
    for (int mi = 0; mi < 2; mi++)
#pragma unroll
        for (int nj = 0; nj < 4; nj++) {
            int r0 = wm + 16 * mi + qr;
            int col = wn + 8 * nj + qc2;
            float sc0 = scale_s[r0];
            float sc1 = scale_s[r0 + 8];
            __nv_bfloat162 lo = __floats2bfloat162_rn(acc[mi][nj][0] * sc0,
                                                      acc[mi][nj][1] * sc0);
            __nv_bfloat162 hi = __floats2bfloat162_rn(acc[mi][nj][2] * sc1,
                                                      acc[mi][nj][3] * sc1);
            *(__nv_bfloat162*)(d_g + (size_t)(bm + r0) * PD_ + col) = lo;
            *(__nv_bfloat162*)(d_g + (size_t)(bm + r0 + 8) * PD_ + col) = hi;
        }
}

// =========================================================================
// Kernel 3: Gram, triangular grid (2080 CTAs). int8 sim, symmetric store.
// Register quant (cvt.pack.sat) -> int8 SMEM staging (primary + transposed
// in ONE pass) -> pure copy-outs.
// =========================================================================
#define TSTRIDE 136
#define ESTR 136
#define GRAM_SMEM_BYTES (2 * 128 * TSTRIDE * 2)   // 69632 (>= 2*128*ESTR)

__global__ __launch_bounds__(256, 2)
void gram_k()
{
    // triangular map: t -> (by, bx), bx >= by, 64x64 tile grid
    int t = blockIdx.x;
    int by = (int)(64.5f - sqrtf(64.5f * 64.5f - 2.0f * (float)t));
    while (by * 64 - by * (by - 1) / 2 > t) by--;
    while ((by + 1) * 64 - (by + 1) * by / 2 <= t) by++;
    int bx = by + (t - (by * 64 - by * (by - 1) / 2));

    extern __shared__ __nv_bfloat16 smg[];
    __nv_bfloat16* As = smg;
    __nv_bfloat16* Bs = smg + 128 * TSTRIDE;

    const int tid  = threadIdx.x;
    const int wid  = tid >> 5;
    const int lane = tid & 31;
    const int m0 = by * 128;
    const int n0 = bx * 128;
    const bool diag = (bx == by);

    const uint4* grow = (const uint4*)d_g;
#pragma unroll
    for (int i = 0; i < 8; i++) {
        int id = tid + i * 256;
        int r  = id >> 4;
        int ch = id & 15;
        uint4 va = grow[(size_t)(m0 + r) * 16 + ch];
        uint4 vb = grow[(size_t)(n0 + r) * 16 + ch];
        *(uint4*)(As + r * TSTRIDE + ch * 8) = va;
        *(uint4*)(Bs + r * TSTRIDE + ch * 8) = vb;
    }
    __syncthreads();

    const int wm = (wid >> 2) * 64;
    const int wn = (wid & 3) * 32;
    const int qr = lane >> 2;
    const int qc = (lane & 3) * 2;

    const int a_row = lane & 15;
    const int a_kof = (lane >> 4) * 8;
    const int g3    = lane >> 3;
    const int b_row = 8 * (g3 >> 1) + (lane & 7);
    const int b_kof = 8 * (g3 & 1);

    float acc[4][4][4];
#pragma unroll
    for (int mi = 0; mi < 4; mi++)
#pragma unroll
        for (int nj = 0; nj < 4; nj++)
#pragma unroll
            for (int q = 0; q < 4; q++) acc[mi][nj][q] = 0.f;

#pragma unroll
    for (int ks = 0; ks < 8; ks++) {
        uint32_t a[4][4], b[4][2];
#pragma unroll
        for (int mi = 0; mi < 4; mi++) {
            uint32_t ad = smem_addr(As + (wm + 16 * mi + a_row) * TSTRIDE
                                       + ks * 16 + a_kof);
            LDSM_X4(a[mi][0], a[mi][1], a[mi][2], a[mi][3], ad);
        }
#pragma unroll
        for (int nj2 = 0; nj2 < 2; nj2++) {
            uint32_t bd = smem_addr(Bs + (wn + 16 * nj2 + b_row) * TSTRIDE
                                       + ks * 16 + b_kof);
            LDSM_X4(b[2 * nj2][0], b[2 * nj2][1],
                    b[2 * nj2 + 1][0], b[2 * nj2 + 1][1], bd);
        }
#pragma unroll
        for (int mi = 0; mi < 4; mi++)
#pragma unroll
            for (int nj = 0; nj < 4; nj++)
                MMA16816(acc[mi][nj], a[mi], b[nj]);
    }

    // ---- single-pass int8 staging: primary tile + transposed tile ----
    __syncthreads();
    int8_t* ES  = (int8_t*)smg;              // [128][ESTR] (m-major)
    int8_t* EST = (int8_t*)smg + 128 * ESTR; // [128][ESTR] (n-major mirror)

#pragma unroll
    for (int mi = 0; mi < 4; mi++)
#pragma unroll
        for (int nj = 0; nj < 4; nj++) {
            int r0 = wm + 16 * mi + qr;
            int c0 = wn + 8 * nj + qc;
            uint32_t plo = pack2_s8(acc[mi][nj][0] * SIM_SCALE,
                                    acc[mi][nj][1] * SIM_SCALE);
            uint32_t phi = pack2_s8(acc[mi][nj][2] * SIM_SCALE,
                                    acc[mi][nj][3] * SIM_SCALE);
            *(uint16_t*)(ES + r0 * ESTR + c0)       = (uint16_t)plo;
            *(uint16_t*)(ES + (r0 + 8) * ESTR + c0) = (uint16_t)phi;
            if (!diag) {
                EST[c0 * ESTR + r0]           = (int8_t)(plo & 0xff);
                EST[(c0 + 1) * ESTR + r0]     = (int8_t)((plo >> 8) & 0xff);
                EST[c0 * ESTR + r0 + 8]       = (int8_t)(phi & 0xff);
                EST[(c0 + 1) * ESTR + r0 + 8] = (int8_t)((phi >> 8) & 0xff);
            }
        }
    __syncthreads();

    // ---- pure copy-outs (8B per thread-iter, fully coalesced) ----
#pragma unroll
    for (int i = 0; i < 8; i++) {
        int id = tid + i * 256;
        int r  = id >> 4;
        int ch = id & 15;
        uint2 v = *(const uint2*)(ES + r * ESTR + ch * 8);
        *(uint2*)(d_sim + (size_t)(m0 + r) * B_ + n0 + ch * 8) = v;
    }
    if (!diag) {
#pragma unroll
        for (int i = 0; i < 8; i++) {
            int id = tid + i * 256;
            int r  = id >> 4;
            int ch = id & 15;
            uint2 v = *(const uint2*)(EST + r * ESTR + ch * 8);
            *(uint2*)(d_sim + (size_t)(n0 + r) * B_ + m0 + ch * 8) = v;
        }
    }
}

// =========================================================================
// Kernel 4: gather + table-based logsumexp + fused deterministic finalize
// =========================================================================
__global__ __launch_bounds__(256)
void gather_lse_k(const int* __restrict__ anchors,
                  const int* __restrict__ positives,
                  const int* __restrict__ negidx,
                  int npairs, float* __restrict__ out)
{
    __shared__ float etab[256];
    __shared__ float ws[8];
    __shared__ int is_last;

    const int tid = threadIdx.x;
    etab[tid] = __expf((float)(tid - 128) * SIM_ISCALE);
    __syncthreads();

    const int p = blockIdx.x * 256 + tid;
    const bool valid = (p < npairs);
    const int pc = valid ? p : 0;

    const int a = anchors[pc];
    const int8_t* __restrict__ row = d_sim + (size_t)a * B_;
    int pidx = positives[pc];
    int nid[NNEG];
#pragma unroll
    for (int j = 0; j < NNEG; j++) nid[j] = negidx[(size_t)pc * NNEG + j];

    int cp = (int)row[pidx];
    float sum = etab[cp + 128];
#pragma unroll
    for (int j = 0; j < NNEG; j++) sum += etab[(int)row[nid[j]] + 128];

    float contrib = valid ? (__logf(sum) - (float)cp * SIM_ISCALE) : 0.f;

    contrib += __shfl_xor_sync(0xffffffffu, contrib, 1);
    contrib += __shfl_xor_sync(0xffffffffu, contrib, 2);
    contrib += __shfl_xor_sync(0xffffffffu, contrib, 4);
    contrib += __shfl_xor_sync(0xffffffffu, contrib, 8);
    contrib += __shfl_xor_sync(0xffffffffu, contrib, 16);
    if ((tid & 31) == 0) ws[tid >> 5] = contrib;
    __syncthreads();
    if (tid < 8) {
        float cv = ws[tid];
        cv += __shfl_xor_sync(0xffu, cv, 1);
        cv += __shfl_xor_sync(0xffu, cv, 2);
        cv += __shfl_xor_sync(0xffu, cv, 4);
        if (tid == 0) d_partials[blockIdx.x] = cv;
    }

    if (tid == 0) {
        __threadfence();
        unsigned t = atomicAdd(&d_done, 1u);
        is_last = (t == gridDim.x - 1);
    }
    __syncthreads();
    if (is_last) {
        __shared__ float sm[256];
        float s = 0.f;
        for (int i = tid; i < (int)gridDim.x; i += 256) s += d_partials[i];
        sm[tid] = s;
        __syncthreads();
        for (int w = 128; w > 0; w >>= 1) {
            if (tid < w) sm[tid] += sm[tid + w];
            __syncthreads();
        }
        if (tid == 0) {
            out[0] = sm[0] / (float)npairs;
            d_done = 0;
        }
    }
}

// =========================================================================
extern "C" void kernel_launch(void* const* d_in, const int* in_sizes, int n_in,
                              void* d_out, int out_size)
{
    const float* x        = (const float*)d_in[0];
    const float* w1       = (const float*)d_in[1];
    const float* w2       = (const float*)d_in[2];
    const int*   anchors  = (const int*)d_in[4];
    const int*   positives= (const int*)d_in[5];
    const int*   negidx   = (const int*)d_in[6];
    const int npairs = in_sizes[4];

    static int attrs_set = 0;
    if (!attrs_set) {
        cudaFuncSetAttribute(gemm1_bf16_k,
                             cudaFuncAttributeMaxDynamicSharedMemorySize, G1_SMEM_BYTES);
        cudaFuncSetAttribute(gemm2_bf16_k,
                             cudaFuncAttributeMaxDynamicSharedMemorySize, G2_SMEM_BYTES);
        cudaFuncSetAttribute(gram_k,
                             cudaFuncAttributeMaxDynamicSharedMemorySize, GRAM_SMEM_BYTES);
        attrs_set = 1;
    }

    convert_k<<<(NCVT + 255) / 256, 256>>>(x, w1, w2);

    dim3 g1(D_ / 128, B_ / 128);
    gemm1_bf16_k<<<g1, 256, G1_SMEM_BYTES>>>();

    gemm2_bf16_k<<<B_ / 64, 256, G2_SMEM_BYTES>>>();

    gram_k<<<2080, 256, GRAM_SMEM_BYTES>>>();   // 64*65/2 upper tiles

    int pblocks = (npairs + 255) / 256;
    gather_lse_k<<<pblocks, 256>>>(anchors, positives, negidx, npairs,
                                   (float*)d_out);
}